// round 10
// baseline (speedup 1.0000x reference)
#include <cuda_runtime.h>
#include <cuda_fp16.h>
#include <cstdint>
#include <math.h>

#define Bb   8
#define Cch  512
#define Nn   4096
#define NHh  8
#define Dd   64

// ---------------- scratch ----------------------------------------------------
__device__ float  g_qn    [Bb*Cch*Nn];   // normalized q, (b,c,n) fp32 (residual)
__device__ __half g_qnt_h [Bb*Nn*Cch];   // normalized q , (b,n,c) half
__device__ __half g_kvnt_h[Bb*Nn*Cch];   // normalized kv, (b,n,c) half
__device__ __half g_Qh    [Bb*Nn*Cch];   // (b,n,c) after rope
__device__ __half g_Kh    [Bb*Nn*Cch];
__device__ __half g_Vh    [Bb*Nn*Cch];
__device__ __half g_attn_h[Bb*Nn*Cch];   // attention out, (b,n,c)
__device__ __half g_Wh    [4*Cch*Cch];   // rounded weights: Wq,Wk,Wv,Wo
__device__ float  g_rope  [Nn*Dd];

// ---------------- PTX helpers ------------------------------------------------
__device__ __forceinline__ uint32_t smem_u32(const void* p) {
    uint32_t a;
    asm("{ .reg .u64 t; cvta.to.shared.u64 t, %1; cvt.u32.u64 %0, t; }" : "=r"(a) : "l"(p));
    return a;
}
__device__ __forceinline__ void cp16(uint32_t dst, const void* src) {
    asm volatile("cp.async.cg.shared.global [%0], [%1], 16;" :: "r"(dst), "l"(src));
}
#define CP_COMMIT() asm volatile("cp.async.commit_group;" ::: "memory")
#define CP_WAIT2()  asm volatile("cp.async.wait_group 2;" ::: "memory")
#define CP_WAIT0()  asm volatile("cp.async.wait_group 0;" ::: "memory")

__device__ __forceinline__ void mma_f16(float* d, const uint32_t* a, const uint32_t* b) {
    asm volatile(
        "mma.sync.aligned.m16n8k16.row.col.f32.f16.f16.f32 "
        "{%0,%1,%2,%3}, {%4,%5,%6,%7}, {%8,%9}, {%0,%1,%2,%3};"
        : "+f"(d[0]), "+f"(d[1]), "+f"(d[2]), "+f"(d[3])
        : "r"(a[0]), "r"(a[1]), "r"(a[2]), "r"(a[3]), "r"(b[0]), "r"(b[1]));
}
__device__ __forceinline__ void ldsm4(uint32_t* r, uint32_t addr) {
    asm volatile("ldmatrix.sync.aligned.m8n8.x4.shared.b16 {%0,%1,%2,%3}, [%4];"
        : "=r"(r[0]), "=r"(r[1]), "=r"(r[2]), "=r"(r[3]) : "r"(addr));
}
__device__ __forceinline__ void ldsm4t(uint32_t* r, uint32_t addr) {
    asm volatile("ldmatrix.sync.aligned.m8n8.x4.trans.shared.b16 {%0,%1,%2,%3}, [%4];"
        : "=r"(r[0]), "=r"(r[1]), "=r"(r[2]), "=r"(r[3]) : "r"(addr));
}
__device__ __forceinline__ uint32_t packh2(float a, float b) {
    __half2 h = __floats2half2_rn(a, b);
    return *(uint32_t*)&h;
}

// ---------------- big-tile GEMM: D[128m x 256n] = A[128xK] x W[256nxK]^T -----
// smem stage: A 128x64h (16KB) + B 256x64h (32KB) = 48KB; 3 stages = 144KB
// row r, 16B chunk c4: off = r*128 + ((c4 ^ (r&7))<<4)
#define STG    49152
#define GSMEM  (3 * STG)
#define NKSTG  8            // K=512 / 64

__device__ __forceinline__ void issue_stage2(uint32_t buf, const char* As, const char* Ws,
                                             uint32_t w0, uint32_t so) {
#pragma unroll
    for (int p = 0; p < 4; p++)
        cp16(buf + w0 + p * 4096, As + so + p * 32768);
#pragma unroll
    for (int p = 0; p < 8; p++)
        cp16(buf + 16384 + w0 + p * 4096, Ws + so + p * 32768);
}

// acc[fm 4][j 8][q 4]; warps: warp_m = wid>>2 (2), warp_n = wid&3 (4); warp 64x64
__device__ __forceinline__ void gemm_mainloop_256(const char* Ab, const char* Wb,
                                                  char* smem, float acc[4][8][4]) {
    uint32_t sb = smem_u32(smem);
    int tid = threadIdx.x;
    int wid = tid >> 5, lane = tid & 31;
    int warp_m = wid >> 2, warp_n = wid & 3;
    int lr = lane & 7, sel = lane >> 3;
    int selLo = sel & 1, selHi = sel >> 1;

    int rA0 = warp_m * 64 + selLo * 8 + lr;      // + fm*16
    int rB0 = warp_n * 64 + selLo * 8 + lr;      // + jp*16

    int r0 = tid >> 3, c4w = tid & 7;
    uint32_t w0 = (uint32_t)(r0 * 128 + ((c4w ^ (r0 & 7)) << 4));
    uint32_t so = (uint32_t)(r0 * 1024 + c4w * 16);

    issue_stage2(sb,       Ab, Wb, w0, so);             CP_COMMIT();
    issue_stage2(sb + STG, Ab + 128, Wb + 128, w0, so); CP_COMMIT();

    int bw = 2;   // next buffer to write
    int br = 0;   // buffer to read
    for (int s = 0; s < NKSTG; s++) {
        if (s + 2 < NKSTG)
            issue_stage2(sb + bw * STG, Ab + (s + 2) * 128, Wb + (s + 2) * 128, w0, so);
        CP_COMMIT();
        CP_WAIT2();
        __syncthreads();

        uint32_t baseA = sb + br * STG;
        uint32_t baseB = baseA + 16384;
#pragma unroll
        for (int kk = 0; kk < 4; kk++) {
            int chunk = 2 * kk + selHi;
            uint32_t af[4][4];
#pragma unroll
            for (int fm = 0; fm < 4; fm++) {
                int r = rA0 + fm * 16;
                ldsm4(af[fm], baseA + (uint32_t)(r * 128 + ((chunk ^ (r & 7)) << 4)));
            }
#pragma unroll
            for (int jp = 0; jp < 4; jp++) {
                int r = rB0 + jp * 16;
                uint32_t bt[4];
                ldsm4(bt, baseB + (uint32_t)(r * 128 + ((chunk ^ (r & 7)) << 4)));
                uint32_t b0[2] = { bt[0], bt[2] };
                uint32_t b1[2] = { bt[1], bt[3] };
#pragma unroll
                for (int fm = 0; fm < 4; fm++) {
                    mma_f16(acc[fm][2 * jp],     af[fm], b0);
                    mma_f16(acc[fm][2 * jp + 1], af[fm], b1);
                }
            }
        }
        __syncthreads();
        br = (br == 2) ? 0 : br + 1;
        bw = (bw == 2) ? 0 : bw + 1;
    }
}

// ---------------- combined QKV projection (+bias, +rope), half out (b,n,c) ---
// grid: (256, 6). y<2: Q tile y; y>=2: fused KV with weight [Wk;Wv], tile y-2.
__global__ __launch_bounds__(256)
void gemm_qkv_h(const __half* __restrict__ Aq, const __half* __restrict__ Akv,
                const __half* __restrict__ Wh,
                const float* __restrict__ bqp, const float* __restrict__ bkp,
                const float* __restrict__ bvp,
                __half* __restrict__ Qo, __half* __restrict__ Ko, __half* __restrict__ Vo) {
    extern __shared__ char smem[];
    int y = blockIdx.y;
    int qpath = (y < 2);
    int cwb0 = qpath ? y * 256 : (y - 2) * 256;
    const __half* A = qpath ? Aq : Akv;
    const __half* W = (qpath ? Wh : Wh + Cch * Cch) + (size_t)cwb0 * 512;
    int m0 = blockIdx.x * 128;

    float acc[4][8][4];
#pragma unroll
    for (int a = 0; a < 4; a++)
#pragma unroll
        for (int j = 0; j < 8; j++)
#pragma unroll
            for (int q = 0; q < 4; q++) acc[a][j][q] = 0.f;

    gemm_mainloop_256((const char*)(A + (size_t)m0 * 512), (const char*)W, smem, acc);

    int tid = threadIdx.x;
    int wid = tid >> 5, lane = tid & 31;
    int gid = lane >> 2, tg = lane & 3;
    int warp_m = wid >> 2, warp_n = wid & 3;

    int cwb = cwb0 + warp_n * 64;                 // weight-col base of this warp
    int is_v = (!qpath) && (cwb >= 512);
    int do_rope = qpath || (!is_v);
    const float* bias = qpath ? bqp : (is_v ? bvp : bkp);
    __half* Out = qpath ? Qo : (is_v ? Vo : Ko);
    int cloc = is_v ? (cwb - 512) : cwb;

#pragma unroll
    for (int fm = 0; fm < 4; fm++) {
#pragma unroll
        for (int rr = 0; rr < 2; rr++) {
            int m = m0 + warp_m * 64 + fm * 16 + gid + rr * 8;
            int n = m & (Nn - 1);
            __half* orow = Out + (size_t)m * 512;
            const float* rp = g_rope + n * 64;
#pragma unroll
            for (int j = 0; j < 8; j++) {
                int col = cloc + j * 8 + 2 * tg;
                float v0 = acc[fm][j][rr * 2]     + __ldg(bias + col);
                float v1 = acc[fm][j][rr * 2 + 1] + __ldg(bias + col + 1);
                if (do_rope) {
                    int d = col & 63;
                    float sn = rp[d], cs = rp[d + 1];
                    float x0 = v0, x1 = v1;
                    v0 = x0 * cs - x1 * sn;
                    v1 = x0 * sn + x1 * cs;
                }
                *(__half2*)(orow + col) = __floats2half2_rn(v0, v1);
            }
        }
    }
}

// ---------------- output projection: fp32 (b,c,n) + bias + residual ----------
// grid: (256, 2); tile 128m x 256c; epilogue staged in two 128-col halves
#define SSTR 132
__global__ __launch_bounds__(256)
void gemm_out_h(const __half* __restrict__ A, const __half* __restrict__ W,
                const float* __restrict__ bo, const float* __restrict__ resid,
                float* __restrict__ Out) {
    extern __shared__ char smem[];
    int m0 = blockIdx.x * 128, c0 = blockIdx.y * 256;

    float acc[4][8][4];
#pragma unroll
    for (int a = 0; a < 4; a++)
#pragma unroll
        for (int j = 0; j < 8; j++)
#pragma unroll
            for (int q = 0; q < 4; q++) acc[a][j][q] = 0.f;

    gemm_mainloop_256((const char*)(A + (size_t)m0 * 512),
                      (const char*)(W + (size_t)c0 * 512), smem, acc);

    int tid = threadIdx.x;
    int wid = tid >> 5, lane = tid & 31;
    int gid = lane >> 2, tg = lane & 3;
    int warp_m = wid >> 2, warp_n = wid & 3;

    float* stage = (float*)smem;
    int b = m0 >> 12, n0 = m0 & (Nn - 1);

#pragma unroll
    for (int h = 0; h < 2; h++) {
        if ((warp_n >> 1) == h) {
#pragma unroll
            for (int fm = 0; fm < 4; fm++) {
                int mb = warp_m * 64 + fm * 16 + gid;
#pragma unroll
                for (int j = 0; j < 8; j++) {
                    int cl = (warp_n & 1) * 64 + j * 8 + 2 * tg;
                    stage[(cl    ) * SSTR + mb    ] = acc[fm][j][0];
                    stage[(cl + 1) * SSTR + mb    ] = acc[fm][j][1];
                    stage[(cl    ) * SSTR + mb + 8] = acc[fm][j][2];
                    stage[(cl + 1) * SSTR + mb + 8] = acc[fm][j][3];
                }
            }
        }
        __syncthreads();
        for (int t = tid; t < 128 * 32; t += 256) {
            int cl = t >> 5, mq = (t & 31) * 4;
            int c = c0 + h * 128 + cl;
            float bc = __ldg(bo + c);
            size_t o = ((size_t)(b * 512 + c)) * 4096 + n0 + mq;
            float4 dv = *(float4*)(stage + cl * SSTR + mq);
            float4 rv = *(const float4*)(resid + o);
            *(float4*)(Out + o) = make_float4(dv.x + bc + rv.x, dv.y + bc + rv.y,
                                              dv.z + bc + rv.z, dv.w + bc + rv.w);
        }
        __syncthreads();
    }
}

// ---------------- all-weights fp32 -> half (one launch) ----------------------
__global__ void w2h_all(const float* __restrict__ w0, const float* __restrict__ w1,
                        const float* __restrict__ w2, const float* __restrict__ w3,
                        __half* __restrict__ dst) {
    int wsel = blockIdx.y;
    const float* src = (wsel == 0) ? w0 : (wsel == 1) ? w1 : (wsel == 2) ? w2 : w3;
    int i = (blockIdx.x * 256 + threadIdx.x) * 4;
    float4 v = *(const float4*)(src + i);
    __half* d = dst + (size_t)wsel * Cch * Cch + i;
    *(__half2*)(d)     = __floats2half2_rn(v.x, v.y);
    *(__half2*)(d + 2) = __floats2half2_rn(v.z, v.w);
}

// ---------------- rope table -------------------------------------------------
__global__ void rope_fill() {
    int idx = blockIdx.x * blockDim.x + threadIdx.x;
    int n = idx >> 5, j = idx & 31;
    float inv = 1.0f / powf(10000.0f, (float)(2 * j) / 64.0f);
    float ang = (float)n * inv;
    g_rope[n * 64 + 2 * j]     = sinf(ang);
    g_rope[n * 64 + 2 * j + 1] = cosf(ang);
}

// ---------------- fused layernorm: (b,c,n) fp32 in -> (b,n,c) half out -------
#define LSTR 72
__global__ __launch_bounds__(128)
void ln_fused(const float* __restrict__ xq, const float* __restrict__ xkv,
              const float* __restrict__ gq, const float* __restrict__ bq,
              const float* __restrict__ gkv, const float* __restrict__ bkv,
              float* __restrict__ out_qn,
              __half* __restrict__ out_qt, __half* __restrict__ out_kvt) {
    __shared__ float gs[512], bs[512];
    __shared__ __half st[128 * LSTR];
    int z = blockIdx.z;
    const float* x   = z ? xkv : xq;
    const float* gam = z ? gkv : gq;
    const float* bet = z ? bkv : bq;
    __half* outT     = z ? out_kvt : out_qt;

    int tid = threadIdx.x;
    for (int c = tid; c < 512; c += 128) { gs[c] = gam[c]; bs[c] = bet[c]; }
    __syncthreads();

    int b = blockIdx.y;
    int n0 = blockIdx.x * 128;
    int n = n0 + tid;
    const float* xp = x + (size_t)b * Cch * Nn + n;

    float s = 0.f, sq = 0.f;
#pragma unroll 8
    for (int c = 0; c < 512; c++) { float v = xp[(size_t)c * Nn]; s += v; sq += v * v; }
    float mu   = s * (1.0f / 512.0f);
    float var  = sq * (1.0f / 512.0f) - mu * mu;
    float rstd = rsqrtf(var + 1e-5f);

    float* op32 = out_qn + (size_t)b * Cch * Nn + n;
    __half* obase = outT + ((size_t)b * Nn + n0) * 512;

    for (int ch = 0; ch < 8; ch++) {
#pragma unroll
        for (int cc = 0; cc < 64; cc += 2) {
            int c = ch * 64 + cc;
            float v0 = xp[(size_t)c * Nn];
            float v1 = xp[(size_t)(c + 1) * Nn];
            float y0 = (v0 - mu) * rstd * gs[c]     + bs[c];
            float y1 = (v1 - mu) * rstd * gs[c + 1] + bs[c + 1];
            if (z == 0) {
                op32[(size_t)c * Nn]       = y0;
                op32[(size_t)(c + 1) * Nn] = y1;
            }
            *(__half2*)(st + tid * LSTR + cc) = __floats2half2_rn(y0, y1);
        }
        __syncthreads();
        for (int t = tid; t < 1024; t += 128) {
            int r = t >> 3, c4 = t & 7;
            *(uint4*)(obase + (size_t)r * 512 + ch * 64 + c4 * 8) =
                *(uint4*)(st + r * LSTR + c4 * 8);
        }
        __syncthreads();
    }
}

// ---------------- windowed attention on tensor cores -------------------------
__global__ __launch_bounds__(128)
void attn_mma(const float* __restrict__ bias_table) {
    __shared__ __align__(16) char sQ[8192];
    __shared__ __align__(16) char sK[8192];
    __shared__ __align__(16) char sV[8192];
    __shared__ float tbl[232];

    int tid = threadIdx.x;
    int w = blockIdx.x, h = blockIdx.y;
    int b = w >> 6, win = w & 63;
    int wy = win >> 3, wx = win & 7;

    for (int t = tid; t < 225; t += 128) tbl[t] = bias_table[t * 8 + h];

    uint32_t uQ = smem_u32(sQ), uK = smem_u32(sK), uV = smem_u32(sV);

    const size_t baseC = ((size_t)b * Nn) * Cch + h * 64;
#pragma unroll
    for (int p = 0; p < 4; p++) {
        int t = p * 128 + tid;
        int r = t >> 3, c4 = t & 7;
        int ri = r >> 3, ci = r & 7;
        int n = (wy * 8 + ri) * 64 + wx * 8 + ci;
        const char* src = (const char*)(g_Qh + baseC + (size_t)n * 512) + c4 * 16;
        const char* srk = (const char*)(g_Kh + baseC + (size_t)n * 512) + c4 * 16;
        const char* srv = (const char*)(g_Vh + baseC + (size_t)n * 512) + c4 * 16;
        uint32_t dst = (uint32_t)(r * 128 + ((c4 ^ (r & 7)) << 4));
        cp16(uQ + dst, src);
        cp16(uK + dst, srk);
        cp16(uV + dst, srv);
    }
    CP_COMMIT();
    CP_WAIT0();
    __syncthreads();

    int wid = tid >> 5, lane = tid & 31;
    int gid = lane >> 2, tg = lane & 3;
    int lr = lane & 7, sel = lane >> 3;
    int selLo = sel & 1, selHi = sel >> 1;
    int m0 = wid * 16;

    int rAq = m0 + selLo * 8 + lr;
    int rB0 = selLo * 8 + lr;

    float sacc[8][4];
#pragma unroll
    for (int j = 0; j < 8; j++)
#pragma unroll
        for (int q = 0; q < 4; q++) sacc[j][q] = 0.f;

#pragma unroll
    for (int kk = 0; kk < 4; kk++) {
        int chunk = 2 * kk + selHi;
        uint32_t af[4];
        ldsm4(af, uQ + (uint32_t)(rAq * 128 + ((chunk ^ (rAq & 7)) << 4)));
#pragma unroll
        for (int jp = 0; jp < 4; jp++) {
            int r = rB0 + jp * 16;
            uint32_t bt[4];
            ldsm4(bt, uK + (uint32_t)(r * 128 + ((chunk ^ (r & 7)) << 4)));
            uint32_t b0[2] = { bt[0], bt[2] };
            uint32_t b1[2] = { bt[1], bt[3] };
            mma_f16(sacc[2 * jp],     af, b0);
            mma_f16(sacc[2 * jp + 1], af, b1);
        }
    }

    int iLo = m0 + gid, iHi = iLo + 8;
    int riLo = iLo >> 3, ciLo = iLo & 7, riHi = iHi >> 3, ciHi = iHi & 7;
#pragma unroll
    for (int j = 0; j < 8; j++) {
#pragma unroll
        for (int q = 0; q < 4; q++) {
            int jc = j * 8 + 2 * tg + (q & 1);
            int rj = jc >> 3, cj = jc & 7;
            int ri = (q < 2) ? riLo : riHi;
            int ci = (q < 2) ? ciLo : ciHi;
            int idx = (ri - rj + 7) * 15 + (ci - cj + 7);
            sacc[j][q] = sacc[j][q] * 0.125f + tbl[idx];
        }
    }

    float mx0 = -1e30f, mx1 = -1e30f;
#pragma unroll
    for (int j = 0; j < 8; j++) {
        mx0 = fmaxf(mx0, fmaxf(sacc[j][0], sacc[j][1]));
        mx1 = fmaxf(mx1, fmaxf(sacc[j][2], sacc[j][3]));
    }
    mx0 = fmaxf(mx0, __shfl_xor_sync(0xffffffffu, mx0, 1));
    mx0 = fmaxf(mx0, __shfl_xor_sync(0xffffffffu, mx0, 2));
    mx1 = fmaxf(mx1, __shfl_xor_sync(0xffffffffu, mx1, 1));
    mx1 = fmaxf(mx1, __shfl_xor_sync(0xffffffffu, mx1, 2));
    float s0 = 0.f, s1 = 0.f;
#pragma unroll
    for (int j = 0; j < 8; j++) {
        sacc[j][0] = __expf(sacc[j][0] - mx0);
        sacc[j][1] = __expf(sacc[j][1] - mx0);
        sacc[j][2] = __expf(sacc[j][2] - mx1);
        sacc[j][3] = __expf(sacc[j][3] - mx1);
        s0 += sacc[j][0] + sacc[j][1];
        s1 += sacc[j][2] + sacc[j][3];
    }
    s0 += __shfl_xor_sync(0xffffffffu, s0, 1);
    s0 += __shfl_xor_sync(0xffffffffu, s0, 2);
    s1 += __shfl_xor_sync(0xffffffffu, s1, 1);
    s1 += __shfl_xor_sync(0xffffffffu, s1, 2);
    float i0v = 1.0f / s0, i1v = 1.0f / s1;
#pragma unroll
    for (int j = 0; j < 8; j++) {
        sacc[j][0] *= i0v; sacc[j][1] *= i0v;
        sacc[j][2] *= i1v; sacc[j][3] *= i1v;
    }

    float oacc[8][4];
#pragma unroll
    for (int j = 0; j < 8; j++)
#pragma unroll
        for (int q = 0; q < 4; q++) oacc[j][q] = 0.f;

#pragma unroll
    for (int kkp = 0; kkp < 4; kkp++) {
        uint32_t af[4];
        af[0] = packh2(sacc[2 * kkp][0],     sacc[2 * kkp][1]);
        af[1] = packh2(sacc[2 * kkp][2],     sacc[2 * kkp][3]);
        af[2] = packh2(sacc[2 * kkp + 1][0], sacc[2 * kkp + 1][1]);
        af[3] = packh2(sacc[2 * kkp + 1][2], sacc[2 * kkp + 1][3]);
        int j0 = kkp * 16;
#pragma unroll
        for (int dp = 0; dp < 4; dp++) {
            int r = j0 + selLo * 8 + lr;
            int chunk = 2 * dp + selHi;
            uint32_t bt[4];
            ldsm4t(bt, uV + (uint32_t)(r * 128 + ((chunk ^ (r & 7)) << 4)));
            uint32_t b0[2] = { bt[0], bt[1] };
            uint32_t b1[2] = { bt[2], bt[3] };
            mma_f16(oacc[2 * dp],     af, b0);
            mma_f16(oacc[2 * dp + 1], af, b1);
        }
    }

    int nLo = (wy * 8 + riLo) * 64 + wx * 8 + ciLo;
    int nHi = (wy * 8 + riHi) * 64 + wx * 8 + ciHi;
    __half* oLo = g_attn_h + baseC + (size_t)nLo * 512;
    __half* oHi = g_attn_h + baseC + (size_t)nHi * 512;
#pragma unroll
    for (int dc = 0; dc < 8; dc++) {
        int d = dc * 8 + 2 * tg;
        *(__half2*)(oLo + d) = __floats2half2_rn(oacc[dc][0], oacc[dc][1]);
        *(__half2*)(oHi + d) = __floats2half2_rn(oacc[dc][2], oacc[dc][3]);
    }
}

// ---------------- launch -----------------------------------------------------
extern "C" void kernel_launch(void* const* d_in, const int* in_sizes, int n_in,
                              void* d_out, int out_size) {
    const float* q          = (const float*)d_in[0];
    const float* kv         = (const float*)d_in[1];
    const float* gq         = (const float*)d_in[2];
    const float* bqln       = (const float*)d_in[3];
    const float* gkv        = (const float*)d_in[4];
    const float* bkvln      = (const float*)d_in[5];
    const float* Wq         = (const float*)d_in[6];
    const float* bq         = (const float*)d_in[7];
    const float* Wk         = (const float*)d_in[8];
    const float* bk         = (const float*)d_in[9];
    const float* Wv         = (const float*)d_in[10];
    const float* bv         = (const float*)d_in[11];
    const float* Wo         = (const float*)d_in[12];
    const float* bo         = (const float*)d_in[13];
    const float* bias_table = (const float*)d_in[14];
    float* out = (float*)d_out;

    float  *p_qn;
    __half *p_qnt, *p_kvnt, *p_Q, *p_K, *p_V, *p_attn, *p_Wh;
    cudaGetSymbolAddress((void**)&p_qn,   g_qn);
    cudaGetSymbolAddress((void**)&p_qnt,  g_qnt_h);
    cudaGetSymbolAddress((void**)&p_kvnt, g_kvnt_h);
    cudaGetSymbolAddress((void**)&p_Q,    g_Qh);
    cudaGetSymbolAddress((void**)&p_K,    g_Kh);
    cudaGetSymbolAddress((void**)&p_V,    g_Vh);
    cudaGetSymbolAddress((void**)&p_attn, g_attn_h);
    cudaGetSymbolAddress((void**)&p_Wh,   g_Wh);

    cudaFuncSetAttribute(gemm_qkv_h, cudaFuncAttributeMaxDynamicSharedMemorySize, GSMEM);
    cudaFuncSetAttribute(gemm_out_h, cudaFuncAttributeMaxDynamicSharedMemorySize, GSMEM);

    w2h_all<<<dim3((Cch * Cch) / 4 / 256, 4), 256>>>(Wq, Wk, Wv, Wo, p_Wh);
    rope_fill<<<512, 256>>>();

    ln_fused<<<dim3(Nn / 128, Bb, 2), 128>>>(q, kv, gq, bqln, gkv, bkvln,
                                             p_qn, p_qnt, p_kvnt);

    gemm_qkv_h<<<dim3(Bb * Nn / 128, 6), 256, GSMEM>>>(
        p_qnt, p_kvnt, p_Wh, bq, bk, bv, p_Q, p_K, p_V);

    attn_mma<<<dim3(Bb * 64, NHh), 128>>>(bias_table);

    gemm_out_h<<<dim3(Bb * Nn / 128, 2), 256, GSMEM>>>(
        p_attn, p_Wh + 3 * (size_t)Cch * Cch, bo, p_qn, out);
}

// round 11
// speedup vs baseline: 1.2469x; 1.2469x over previous
#include <cuda_runtime.h>
#include <cuda_fp16.h>
#include <cstdint>
#include <math.h>

#define Bb   8
#define Cch  512
#define Nn   4096
#define NHh  8
#define Dd   64

// ---------------- scratch ----------------------------------------------------
__device__ float  g_qn    [Bb*Cch*Nn];   // normalized q, (b,c,n) fp32 (residual)
__device__ __half g_qnt_h [Bb*Nn*Cch];   // normalized q , (b,n,c) half
__device__ __half g_kvnt_h[Bb*Nn*Cch];   // normalized kv, (b,n,c) half
__device__ __half g_Qh    [Bb*Nn*Cch];   // (b,n,c) after rope
__device__ __half g_Kh    [Bb*Nn*Cch];
__device__ __half g_Vh    [Bb*Nn*Cch];
__device__ __half g_attn_h[Bb*Nn*Cch];   // attention out, (b,n,c)
__device__ __half g_Wh    [4*Cch*Cch];   // rounded weights: Wq,Wk,Wv,Wo
__device__ float  g_rope  [Nn*Dd];

// ---------------- PTX helpers ------------------------------------------------
__device__ __forceinline__ uint32_t smem_u32(const void* p) {
    uint32_t a;
    asm("{ .reg .u64 t; cvta.to.shared.u64 t, %1; cvt.u32.u64 %0, t; }" : "=r"(a) : "l"(p));
    return a;
}
__device__ __forceinline__ void cp16(uint32_t dst, const void* src) {
    asm volatile("cp.async.cg.shared.global [%0], [%1], 16;" :: "r"(dst), "l"(src));
}
#define CP_COMMIT() asm volatile("cp.async.commit_group;" ::: "memory")
#define CP_WAIT1()  asm volatile("cp.async.wait_group 1;" ::: "memory")
#define CP_WAIT0()  asm volatile("cp.async.wait_group 0;" ::: "memory")

__device__ __forceinline__ void mma_f16(float* d, const uint32_t* a, const uint32_t* b) {
    asm volatile(
        "mma.sync.aligned.m16n8k16.row.col.f32.f16.f16.f32 "
        "{%0,%1,%2,%3}, {%4,%5,%6,%7}, {%8,%9}, {%0,%1,%2,%3};"
        : "+f"(d[0]), "+f"(d[1]), "+f"(d[2]), "+f"(d[3])
        : "r"(a[0]), "r"(a[1]), "r"(a[2]), "r"(a[3]), "r"(b[0]), "r"(b[1]));
}
__device__ __forceinline__ void ldsm4(uint32_t* r, uint32_t addr) {
    asm volatile("ldmatrix.sync.aligned.m8n8.x4.shared.b16 {%0,%1,%2,%3}, [%4];"
        : "=r"(r[0]), "=r"(r[1]), "=r"(r[2]), "=r"(r[3]) : "r"(addr));
}
__device__ __forceinline__ void ldsm4t(uint32_t* r, uint32_t addr) {
    asm volatile("ldmatrix.sync.aligned.m8n8.x4.trans.shared.b16 {%0,%1,%2,%3}, [%4];"
        : "=r"(r[0]), "=r"(r[1]), "=r"(r[2]), "=r"(r[3]) : "r"(addr));
}
__device__ __forceinline__ uint32_t packh2(float a, float b) {
    __half2 h = __floats2half2_rn(a, b);
    return *(uint32_t*)&h;
}

// smem tile: 128 rows x 64 halves (128B/row); 16B chunk c4 at r*128 + ((c4^(r&7))<<4)
#define STAGE_B 32768
#define GSMEM   (3 * STAGE_B)

__device__ __forceinline__ void issue_stage(uint32_t sbuf, const char* as, const char* ws,
                                            uint32_t w0) {
#pragma unroll
    for (int p = 0; p < 4; p++) {
        cp16(sbuf + w0 + p * 4096,         as + p * 32768);
        cp16(sbuf + 16384 + w0 + p * 4096, ws + p * 32768);
    }
}

// ---------------- mainloop: D[128m x 128c] = A[128x512] x W[128x512]^T -------
// single barrier per stage: wait(group s) -> sync -> issue(s+2) -> compute(s)
__device__ __forceinline__ void gemm_mainloop_h(const __half* __restrict__ A,
                                                const __half* __restrict__ W,
                                                char* smem, float acc[2][8][4],
                                                int m0, int c0) {
    uint32_t sb = smem_u32(smem);
    int tid = threadIdx.x;
    int wid = tid >> 5, lane = tid & 31;
    int warp_m = wid >> 1, warp_n = wid & 1;
    int lr = lane & 7, sel = lane >> 3;
    int selLo = sel & 1, selHi = sel >> 1;

    int rA0 = warp_m * 32 + selLo * 8 + lr;
    int rB0 = warp_n * 64 + selLo * 8 + lr;

    const char* Ab = (const char*)(A + (size_t)m0 * 512);
    const char* Wb = (const char*)(W + (size_t)c0 * 512);
    int r0 = tid >> 3, c4w = tid & 7;
    uint32_t w0 = (uint32_t)(r0 * 128 + ((c4w ^ (r0 & 7)) << 4));
    uint32_t so = (uint32_t)(r0 * 1024 + c4w * 16);

    issue_stage(sb,           Ab + so,       Wb + so,       w0); CP_COMMIT();
    issue_stage(sb + STAGE_B, Ab + so + 128, Wb + so + 128, w0); CP_COMMIT();

    for (int s = 0; s < 8; s++) {
        CP_WAIT1();            // this thread's group s complete
        __syncthreads();       // all threads' data visible; prior compute done
        if (s + 2 < 8)
            issue_stage(sb + ((s + 2) % 3) * STAGE_B,
                        Ab + so + (s + 2) * 128, Wb + so + (s + 2) * 128, w0);
        CP_COMMIT();           // unconditional: keeps group indices aligned

        uint32_t baseA = sb + (s % 3) * STAGE_B;
        uint32_t baseB = baseA + 16384;
#pragma unroll
        for (int kk = 0; kk < 4; kk++) {
            int chunk = 2 * kk + selHi;
            uint32_t af[2][4];
#pragma unroll
            for (int fm = 0; fm < 2; fm++) {
                int r = rA0 + fm * 16;
                ldsm4(af[fm], baseA + (uint32_t)(r * 128 + ((chunk ^ (r & 7)) << 4)));
            }
#pragma unroll
            for (int jp = 0; jp < 4; jp++) {
                int r = rB0 + jp * 16;
                uint32_t bt[4];
                ldsm4(bt, baseB + (uint32_t)(r * 128 + ((chunk ^ (r & 7)) << 4)));
                uint32_t b0[2] = { bt[0], bt[2] };
                uint32_t b1[2] = { bt[1], bt[3] };
                mma_f16(acc[0][2 * jp],     af[0], b0);
                mma_f16(acc[1][2 * jp],     af[1], b0);
                mma_f16(acc[0][2 * jp + 1], af[0], b1);
                mma_f16(acc[1][2 * jp + 1], af[1], b1);
            }
        }
    }
    __syncthreads();           // smem reusable by epilogue
}

// ---------------- combined QKV projection (+bias, +rope), half out (b,n,c) ---
#define QSTR 136
__global__ __launch_bounds__(256, 2)
void gemm_qkv_h(const __half* __restrict__ Aq, const __half* __restrict__ Akv,
                const __half* __restrict__ Wh,
                const float* __restrict__ bqp, const float* __restrict__ bkp,
                const float* __restrict__ bvp,
                __half* __restrict__ Qo, __half* __restrict__ Ko, __half* __restrict__ Vo) {
    extern __shared__ char smem[];
    int z = blockIdx.z;
    const __half* A = z ? Akv : Aq;
    const __half* W = Wh + (size_t)z * Cch * Cch;
    const float* bias = (z == 0) ? bqp : (z == 1) ? bkp : bvp;
    __half* Out = (z == 0) ? Qo : (z == 1) ? Ko : Vo;
    int do_rope = (z < 2);

    int m0 = blockIdx.x * 128, c0 = blockIdx.y * 128;
    float acc[2][8][4];
#pragma unroll
    for (int a = 0; a < 2; a++)
#pragma unroll
        for (int j = 0; j < 8; j++)
#pragma unroll
            for (int q = 0; q < 4; q++) acc[a][j][q] = 0.f;

    gemm_mainloop_h(A, W, smem, acc, m0, c0);

    int tid = threadIdx.x;
    int wid = tid >> 5, lane = tid & 31;
    int gid = lane >> 2, tg = lane & 3;
    int warp_m = wid >> 1, warp_n = wid & 1;

    // stage rope+bias result into smem (conflict-free), then coalesced copy-out
    __half* stage = (__half*)smem;
#pragma unroll
    for (int fm = 0; fm < 2; fm++) {
#pragma unroll
        for (int rr = 0; rr < 2; rr++) {
            int ml = warp_m * 32 + fm * 16 + gid + rr * 8;
            int n = (m0 + ml) & (Nn - 1);
            const float* rp = g_rope + n * 64;
#pragma unroll
            for (int j = 0; j < 8; j++) {
                int col = warp_n * 64 + j * 8 + 2 * tg;
                float v0 = acc[fm][j][rr * 2]     + __ldg(bias + c0 + col);
                float v1 = acc[fm][j][rr * 2 + 1] + __ldg(bias + c0 + col + 1);
                if (do_rope) {
                    int d = col & 63;
                    float sn = rp[d], cs = rp[d + 1];
                    float x0 = v0, x1 = v1;
                    v0 = x0 * cs - x1 * sn;
                    v1 = x0 * sn + x1 * cs;
                }
                *(__half2*)(stage + ml * QSTR + col) = __floats2half2_rn(v0, v1);
            }
        }
    }
    __syncthreads();
#pragma unroll
    for (int p = 0; p < 8; p++) {
        int idx = p * 256 + tid;
        int ml = idx >> 4, c8 = idx & 15;
        *(uint4*)(Out + (size_t)(m0 + ml) * 512 + c0 + c8 * 8) =
            *(uint4*)(stage + ml * QSTR + c8 * 8);
    }
}

// ---------------- output projection: fp32 (b,c,n) + bias + residual ----------
#define SSTR 132
__global__ __launch_bounds__(256, 2)
void gemm_out_h(const __half* __restrict__ A, const __half* __restrict__ W,
                const float* __restrict__ bo, const float* __restrict__ resid,
                float* __restrict__ Out) {
    extern __shared__ char smem[];
    int m0 = blockIdx.x * 128, c0 = blockIdx.y * 128;
    float acc[2][8][4];
#pragma unroll
    for (int a = 0; a < 2; a++)
#pragma unroll
        for (int j = 0; j < 8; j++)
#pragma unroll
            for (int q = 0; q < 4; q++) acc[a][j][q] = 0.f;

    gemm_mainloop_h(A, W, smem, acc, m0, c0);

    int tid = threadIdx.x;
    int wid = tid >> 5, lane = tid & 31;
    int gid = lane >> 2, tg = lane & 3;
    int warp_m = wid >> 1, warp_n = wid & 1;

    float* stage = (float*)smem;
#pragma unroll
    for (int fm = 0; fm < 2; fm++) {
        int mb = warp_m * 32 + fm * 16 + gid;
#pragma unroll
        for (int j = 0; j < 8; j++) {
            int cl = warp_n * 64 + j * 8 + 2 * tg;
            stage[(cl    ) * SSTR + mb    ] = acc[fm][j][0];
            stage[(cl + 1) * SSTR + mb    ] = acc[fm][j][1];
            stage[(cl    ) * SSTR + mb + 8] = acc[fm][j][2];
            stage[(cl + 1) * SSTR + mb + 8] = acc[fm][j][3];
        }
    }
    __syncthreads();

    int b = m0 >> 12, n0 = m0 & (Nn - 1);
    for (int t = tid; t < 128 * 32; t += 256) {
        int cl = t >> 5, mq = (t & 31) * 4;
        int c = c0 + cl;
        float bc = __ldg(bo + c);
        size_t o = ((size_t)(b * 512 + c)) * 4096 + n0 + mq;
        float4 dv = *(float4*)(stage + cl * SSTR + mq);
        float4 rv = *(const float4*)(resid + o);
        *(float4*)(Out + o) = make_float4(dv.x + bc + rv.x, dv.y + bc + rv.y,
                                          dv.z + bc + rv.z, dv.w + bc + rv.w);
    }
}

// ---------------- all-weights fp32 -> half (one launch) ----------------------
__global__ void w2h_all(const float* __restrict__ w0, const float* __restrict__ w1,
                        const float* __restrict__ w2, const float* __restrict__ w3,
                        __half* __restrict__ dst) {
    int wsel = blockIdx.y;
    const float* src = (wsel == 0) ? w0 : (wsel == 1) ? w1 : (wsel == 2) ? w2 : w3;
    int i = (blockIdx.x * 256 + threadIdx.x) * 4;
    float4 v = *(const float4*)(src + i);
    __half* d = dst + (size_t)wsel * Cch * Cch + i;
    *(__half2*)(d)     = __floats2half2_rn(v.x, v.y);
    *(__half2*)(d + 2) = __floats2half2_rn(v.z, v.w);
}

// ---------------- rope table -------------------------------------------------
__global__ void rope_fill() {
    int idx = blockIdx.x * blockDim.x + threadIdx.x;
    int n = idx >> 5, j = idx & 31;
    float inv = 1.0f / powf(10000.0f, (float)(2 * j) / 64.0f);
    float ang = (float)n * inv;
    g_rope[n * 64 + 2 * j]     = sinf(ang);
    g_rope[n * 64 + 2 * j + 1] = cosf(ang);
}

// ---------------- fused layernorm: (b,c,n) fp32 in -> (b,n,c) half out -------
#define LSTR 72
__global__ __launch_bounds__(128)
void ln_fused(const float* __restrict__ xq, const float* __restrict__ xkv,
              const float* __restrict__ gq, const float* __restrict__ bq,
              const float* __restrict__ gkv, const float* __restrict__ bkv,
              float* __restrict__ out_qn,
              __half* __restrict__ out_qt, __half* __restrict__ out_kvt) {
    __shared__ float gs[512], bs[512];
    __shared__ __half st[128 * LSTR];
    int z = blockIdx.z;
    const float* x   = z ? xkv : xq;
    const float* gam = z ? gkv : gq;
    const float* bet = z ? bkv : bq;
    __half* outT     = z ? out_kvt : out_qt;

    int tid = threadIdx.x;
    for (int c = tid; c < 512; c += 128) { gs[c] = gam[c]; bs[c] = bet[c]; }
    __syncthreads();

    int b = blockIdx.y;
    int n0 = blockIdx.x * 128;
    int n = n0 + tid;
    const float* xp = x + (size_t)b * Cch * Nn + n;

    float s = 0.f, sq = 0.f;
#pragma unroll 8
    for (int c = 0; c < 512; c++) { float v = xp[(size_t)c * Nn]; s += v; sq += v * v; }
    float mu   = s * (1.0f / 512.0f);
    float var  = sq * (1.0f / 512.0f) - mu * mu;
    float rstd = rsqrtf(var + 1e-5f);

    float* op32 = out_qn + (size_t)b * Cch * Nn + n;
    __half* obase = outT + ((size_t)b * Nn + n0) * 512;

    for (int ch = 0; ch < 8; ch++) {
#pragma unroll
        for (int cc = 0; cc < 64; cc += 2) {
            int c = ch * 64 + cc;
            float v0 = xp[(size_t)c * Nn];
            float v1 = xp[(size_t)(c + 1) * Nn];
            float y0 = (v0 - mu) * rstd * gs[c]     + bs[c];
            float y1 = (v1 - mu) * rstd * gs[c + 1] + bs[c + 1];
            if (z == 0) {
                op32[(size_t)c * Nn]       = y0;
                op32[(size_t)(c + 1) * Nn] = y1;
            }
            *(__half2*)(st + tid * LSTR + cc) = __floats2half2_rn(y0, y1);
        }
        __syncthreads();
        for (int t = tid; t < 1024; t += 128) {
            int r = t >> 3, c4 = t & 7;
            *(uint4*)(obase + (size_t)r * 512 + ch * 64 + c4 * 8) =
                *(uint4*)(st + r * LSTR + c4 * 8);
        }
        __syncthreads();
    }
}

// ---------------- windowed attention on tensor cores -------------------------
__global__ __launch_bounds__(128)
void attn_mma(const float* __restrict__ bias_table) {
    __shared__ __align__(16) char sQ[8192];
    __shared__ __align__(16) char sK[8192];
    __shared__ __align__(16) char sV[8192];
    __shared__ float tbl[232];

    int tid = threadIdx.x;
    int w = blockIdx.x, h = blockIdx.y;
    int b = w >> 6, win = w & 63;
    int wy = win >> 3, wx = win & 7;

    for (int t = tid; t < 225; t += 128) tbl[t] = bias_table[t * 8 + h];

    uint32_t uQ = smem_u32(sQ), uK = smem_u32(sK), uV = smem_u32(sV);

    const size_t baseC = ((size_t)b * Nn) * Cch + h * 64;
#pragma unroll
    for (int p = 0; p < 4; p++) {
        int t = p * 128 + tid;
        int r = t >> 3, c4 = t & 7;
        int ri = r >> 3, ci = r & 7;
        int n = (wy * 8 + ri) * 64 + wx * 8 + ci;
        const char* src = (const char*)(g_Qh + baseC + (size_t)n * 512) + c4 * 16;
        const char* srk = (const char*)(g_Kh + baseC + (size_t)n * 512) + c4 * 16;
        const char* srv = (const char*)(g_Vh + baseC + (size_t)n * 512) + c4 * 16;
        uint32_t dst = (uint32_t)(r * 128 + ((c4 ^ (r & 7)) << 4));
        cp16(uQ + dst, src);
        cp16(uK + dst, srk);
        cp16(uV + dst, srv);
    }
    CP_COMMIT();
    CP_WAIT0();
    __syncthreads();

    int wid = tid >> 5, lane = tid & 31;
    int gid = lane >> 2, tg = lane & 3;
    int lr = lane & 7, sel = lane >> 3;
    int selLo = sel & 1, selHi = sel >> 1;
    int m0 = wid * 16;

    int rAq = m0 + selLo * 8 + lr;
    int rB0 = selLo * 8 + lr;

    float sacc[8][4];
#pragma unroll
    for (int j = 0; j < 8; j++)
#pragma unroll
        for (int q = 0; q < 4; q++) sacc[j][q] = 0.f;

#pragma unroll
    for (int kk = 0; kk < 4; kk++) {
        int chunk = 2 * kk + selHi;
        uint32_t af[4];
        ldsm4(af, uQ + (uint32_t)(rAq * 128 + ((chunk ^ (rAq & 7)) << 4)));
#pragma unroll
        for (int jp = 0; jp < 4; jp++) {
            int r = rB0 + jp * 16;
            uint32_t bt[4];
            ldsm4(bt, uK + (uint32_t)(r * 128 + ((chunk ^ (r & 7)) << 4)));
            uint32_t b0[2] = { bt[0], bt[2] };
            uint32_t b1[2] = { bt[1], bt[3] };
            mma_f16(sacc[2 * jp],     af, b0);
            mma_f16(sacc[2 * jp + 1], af, b1);
        }
    }

    int iLo = m0 + gid, iHi = iLo + 8;
    int riLo = iLo >> 3, ciLo = iLo & 7, riHi = iHi >> 3, ciHi = iHi & 7;
#pragma unroll
    for (int j = 0; j < 8; j++) {
#pragma unroll
        for (int q = 0; q < 4; q++) {
            int jc = j * 8 + 2 * tg + (q & 1);
            int rj = jc >> 3, cj = jc & 7;
            int ri = (q < 2) ? riLo : riHi;
            int ci = (q < 2) ? ciLo : ciHi;
            int idx = (ri - rj + 7) * 15 + (ci - cj + 7);
            sacc[j][q] = sacc[j][q] * 0.125f + tbl[idx];
        }
    }

    float mx0 = -1e30f, mx1 = -1e30f;
#pragma unroll
    for (int j = 0; j < 8; j++) {
        mx0 = fmaxf(mx0, fmaxf(sacc[j][0], sacc[j][1]));
        mx1 = fmaxf(mx1, fmaxf(sacc[j][2], sacc[j][3]));
    }
    mx0 = fmaxf(mx0, __shfl_xor_sync(0xffffffffu, mx0, 1));
    mx0 = fmaxf(mx0, __shfl_xor_sync(0xffffffffu, mx0, 2));
    mx1 = fmaxf(mx1, __shfl_xor_sync(0xffffffffu, mx1, 1));
    mx1 = fmaxf(mx1, __shfl_xor_sync(0xffffffffu, mx1, 2));
    float s0 = 0.f, s1 = 0.f;
#pragma unroll
    for (int j = 0; j < 8; j++) {
        sacc[j][0] = __expf(sacc[j][0] - mx0);
        sacc[j][1] = __expf(sacc[j][1] - mx0);
        sacc[j][2] = __expf(sacc[j][2] - mx1);
        sacc[j][3] = __expf(sacc[j][3] - mx1);
        s0 += sacc[j][0] + sacc[j][1];
        s1 += sacc[j][2] + sacc[j][3];
    }
    s0 += __shfl_xor_sync(0xffffffffu, s0, 1);
    s0 += __shfl_xor_sync(0xffffffffu, s0, 2);
    s1 += __shfl_xor_sync(0xffffffffu, s1, 1);
    s1 += __shfl_xor_sync(0xffffffffu, s1, 2);
    float i0v = 1.0f / s0, i1v = 1.0f / s1;
#pragma unroll
    for (int j = 0; j < 8; j++) {
        sacc[j][0] *= i0v; sacc[j][1] *= i0v;
        sacc[j][2] *= i1v; sacc[j][3] *= i1v;
    }

    float oacc[8][4];
#pragma unroll
    for (int j = 0; j < 8; j++)
#pragma unroll
        for (int q = 0; q < 4; q++) oacc[j][q] = 0.f;

#pragma unroll
    for (int kkp = 0; kkp < 4; kkp++) {
        uint32_t af[4];
        af[0] = packh2(sacc[2 * kkp][0],     sacc[2 * kkp][1]);
        af[1] = packh2(sacc[2 * kkp][2],     sacc[2 * kkp][3]);
        af[2] = packh2(sacc[2 * kkp + 1][0], sacc[2 * kkp + 1][1]);
        af[3] = packh2(sacc[2 * kkp + 1][2], sacc[2 * kkp + 1][3]);
        int j0 = kkp * 16;
#pragma unroll
        for (int dp = 0; dp < 4; dp++) {
            int r = j0 + selLo * 8 + lr;
            int chunk = 2 * dp + selHi;
            uint32_t bt[4];
            ldsm4t(bt, uV + (uint32_t)(r * 128 + ((chunk ^ (r & 7)) << 4)));
            uint32_t b0[2] = { bt[0], bt[1] };
            uint32_t b1[2] = { bt[2], bt[3] };
            mma_f16(oacc[2 * dp],     af, b0);
            mma_f16(oacc[2 * dp + 1], af, b1);
        }
    }

    int nLo = (wy * 8 + riLo) * 64 + wx * 8 + ciLo;
    int nHi = (wy * 8 + riHi) * 64 + wx * 8 + ciHi;
    __half* oLo = g_attn_h + baseC + (size_t)nLo * 512;
    __half* oHi = g_attn_h + baseC + (size_t)nHi * 512;
#pragma unroll
    for (int dc = 0; dc < 8; dc++) {
        int d = dc * 8 + 2 * tg;
        *(__half2*)(oLo + d) = __floats2half2_rn(oacc[dc][0], oacc[dc][1]);
        *(__half2*)(oHi + d) = __floats2half2_rn(oacc[dc][2], oacc[dc][3]);
    }
}

// ---------------- launch -----------------------------------------------------
extern "C" void kernel_launch(void* const* d_in, const int* in_sizes, int n_in,
                              void* d_out, int out_size) {
    const float* q          = (const float*)d_in[0];
    const float* kv         = (const float*)d_in[1];
    const float* gq         = (const float*)d_in[2];
    const float* bqln       = (const float*)d_in[3];
    const float* gkv        = (const float*)d_in[4];
    const float* bkvln      = (const float*)d_in[5];
    const float* Wq         = (const float*)d_in[6];
    const float* bq         = (const float*)d_in[7];
    const float* Wk         = (const float*)d_in[8];
    const float* bk         = (const float*)d_in[9];
    const float* Wv         = (const float*)d_in[10];
    const float* bv         = (const float*)d_in[11];
    const float* Wo         = (const float*)d_in[12];
    const float* bo         = (const float*)d_in[13];
    const float* bias_table = (const float*)d_in[14];
    float* out = (float*)d_out;

    float  *p_qn;
    __half *p_qnt, *p_kvnt, *p_Q, *p_K, *p_V, *p_attn, *p_Wh;
    cudaGetSymbolAddress((void**)&p_qn,   g_qn);
    cudaGetSymbolAddress((void**)&p_qnt,  g_qnt_h);
    cudaGetSymbolAddress((void**)&p_kvnt, g_kvnt_h);
    cudaGetSymbolAddress((void**)&p_Q,    g_Qh);
    cudaGetSymbolAddress((void**)&p_K,    g_Kh);
    cudaGetSymbolAddress((void**)&p_V,    g_Vh);
    cudaGetSymbolAddress((void**)&p_attn, g_attn_h);
    cudaGetSymbolAddress((void**)&p_Wh,   g_Wh);

    cudaFuncSetAttribute(gemm_qkv_h, cudaFuncAttributeMaxDynamicSharedMemorySize, GSMEM);
    cudaFuncSetAttribute(gemm_out_h, cudaFuncAttributeMaxDynamicSharedMemorySize, GSMEM);

    w2h_all<<<dim3((Cch * Cch) / 4 / 256, 4), 256>>>(Wq, Wk, Wv, Wo, p_Wh);
    rope_fill<<<512, 256>>>();

    ln_fused<<<dim3(Nn / 128, Bb, 2), 128>>>(q, kv, gq, bqln, gkv, bkvln,
                                             p_qn, p_qnt, p_kvnt);

    gemm_qkv_h<<<dim3(Bb * Nn / 128, Cch / 128, 3), 256, GSMEM>>>(
        p_qnt, p_kvnt, p_Wh, bq, bk, bv, p_Q, p_K, p_V);

    attn_mma<<<dim3(Bb * 64, NHh), 128>>>(bias_table);

    gemm_out_h<<<dim3(Bb * Nn / 128, Cch / 128), 256, GSMEM>>>(
        p_attn, p_Wh + 3 * (size_t)Cch * Cch, bo, p_qn, out);
}

// round 12
// speedup vs baseline: 1.5154x; 1.2153x over previous
#include <cuda_runtime.h>
#include <cuda_fp16.h>
#include <cstdint>
#include <math.h>

#define Bb   8
#define Cch  512
#define Nn   4096
#define NHh  8
#define Dd   64

// ---------------- scratch ----------------------------------------------------
__device__ __half g_qnt_h [Bb*Nn*Cch];   // normalized q , (b,n,c) half (GEMM A + residual)
__device__ __half g_kvnt_h[Bb*Nn*Cch];   // normalized kv, (b,n,c) half
__device__ __half g_Qh    [Bb*Nn*Cch];   // (b,n,c) after rope
__device__ __half g_Kh    [Bb*Nn*Cch];
__device__ __half g_Vh    [Bb*Nn*Cch];
__device__ __half g_attn_h[Bb*Nn*Cch];   // attention out, (b,n,c)
__device__ __half g_Wh    [4*Cch*Cch];   // rounded weights: Wq,Wk,Wv,Wo
__device__ float  g_rope  [Nn*Dd];

// ---------------- PTX helpers ------------------------------------------------
__device__ __forceinline__ uint32_t smem_u32(const void* p) {
    uint32_t a;
    asm("{ .reg .u64 t; cvta.to.shared.u64 t, %1; cvt.u32.u64 %0, t; }" : "=r"(a) : "l"(p));
    return a;
}
__device__ __forceinline__ void cp16(uint32_t dst, const void* src) {
    asm volatile("cp.async.cg.shared.global [%0], [%1], 16;" :: "r"(dst), "l"(src));
}
#define CP_COMMIT() asm volatile("cp.async.commit_group;" ::: "memory")
#define CP_WAIT1()  asm volatile("cp.async.wait_group 1;" ::: "memory")
#define CP_WAIT0()  asm volatile("cp.async.wait_group 0;" ::: "memory")

__device__ __forceinline__ void mma_f16(float* d, const uint32_t* a, const uint32_t* b) {
    asm volatile(
        "mma.sync.aligned.m16n8k16.row.col.f32.f16.f16.f32 "
        "{%0,%1,%2,%3}, {%4,%5,%6,%7}, {%8,%9}, {%0,%1,%2,%3};"
        : "+f"(d[0]), "+f"(d[1]), "+f"(d[2]), "+f"(d[3])
        : "r"(a[0]), "r"(a[1]), "r"(a[2]), "r"(a[3]), "r"(b[0]), "r"(b[1]));
}
__device__ __forceinline__ void ldsm4(uint32_t* r, uint32_t addr) {
    asm volatile("ldmatrix.sync.aligned.m8n8.x4.shared.b16 {%0,%1,%2,%3}, [%4];"
        : "=r"(r[0]), "=r"(r[1]), "=r"(r[2]), "=r"(r[3]) : "r"(addr));
}
__device__ __forceinline__ void ldsm4t(uint32_t* r, uint32_t addr) {
    asm volatile("ldmatrix.sync.aligned.m8n8.x4.trans.shared.b16 {%0,%1,%2,%3}, [%4];"
        : "=r"(r[0]), "=r"(r[1]), "=r"(r[2]), "=r"(r[3]) : "r"(addr));
}
__device__ __forceinline__ uint32_t packh2(float a, float b) {
    __half2 h = __floats2half2_rn(a, b);
    return *(uint32_t*)&h;
}
// swizzled row-constant: row r, 16B chunk c: off = rowc(r) ^ (c<<4), rowc = r*128 + ((r&7)<<4)
__device__ __forceinline__ uint32_t rowc(int r) {
    return (uint32_t)(r * 128 + ((r & 7) << 4));
}

#define STAGE_B 32768
#define GSMEM   (3 * STAGE_B)

__device__ __forceinline__ void issue_stage(uint32_t sbuf, const char* as, const char* ws,
                                            uint32_t w0) {
#pragma unroll
    for (int p = 0; p < 4; p++) {
        cp16(sbuf + w0 + p * 4096,         as + p * 32768);
        cp16(sbuf + 16384 + w0 + p * 4096, ws + p * 32768);
    }
}

// ---------------- mainloop: D[128m x 128c] = A[128x512] x W[128x512]^T -------
__device__ __forceinline__ void gemm_mainloop_h(const __half* __restrict__ A,
                                                const __half* __restrict__ W,
                                                char* smem, float acc[2][8][4],
                                                int m0, int c0) {
    uint32_t sb = smem_u32(smem);
    int tid = threadIdx.x;
    int wid = tid >> 5, lane = tid & 31;
    int warp_m = wid >> 1, warp_n = wid & 1;
    int lr = lane & 7, sel = lane >> 3;
    int selLo = sel & 1, selHi = sel >> 1;

    uint32_t rowA0 = rowc(warp_m * 32 + selLo * 8 + lr);
    uint32_t rowA1 = rowc(warp_m * 32 + selLo * 8 + lr + 16);
    uint32_t rowB[4];
#pragma unroll
    for (int jp = 0; jp < 4; jp++)
        rowB[jp] = rowc(warp_n * 64 + selLo * 8 + lr + jp * 16);

    const char* Ab = (const char*)(A + (size_t)m0 * 512);
    const char* Wb = (const char*)(W + (size_t)c0 * 512);
    int r0 = tid >> 3, c4w = tid & 7;
    uint32_t w0 = (uint32_t)(r0 * 128 + ((c4w ^ (r0 & 7)) << 4));
    uint32_t so = (uint32_t)(r0 * 1024 + c4w * 16);

    issue_stage(sb,           Ab + so,       Wb + so,       w0); CP_COMMIT();
    issue_stage(sb + STAGE_B, Ab + so + 128, Wb + so + 128, w0); CP_COMMIT();

    for (int s = 0; s < 8; s++) {
        CP_WAIT1();
        __syncthreads();
        if (s + 2 < 8)
            issue_stage(sb + ((s + 2) % 3) * STAGE_B,
                        Ab + so + (s + 2) * 128, Wb + so + (s + 2) * 128, w0);
        CP_COMMIT();

        uint32_t baseA = sb + (s % 3) * STAGE_B;
        uint32_t baseB = baseA + 16384;
#pragma unroll
        for (int kk = 0; kk < 4; kk++) {
            uint32_t xm = (uint32_t)((2 * kk + selHi) << 4);
            uint32_t af[2][4];
            ldsm4(af[0], baseA + (rowA0 ^ xm));
            ldsm4(af[1], baseA + (rowA1 ^ xm));
            uint32_t bt[4];
            ldsm4(bt, baseB + (rowB[0] ^ xm));
#pragma unroll
            for (int jp = 0; jp < 4; jp++) {
                uint32_t btn[4];
                if (jp < 3) ldsm4(btn, baseB + (rowB[jp + 1] ^ xm));
                uint32_t b0[2] = { bt[0], bt[2] };
                uint32_t b1[2] = { bt[1], bt[3] };
                mma_f16(acc[0][2 * jp],     af[0], b0);
                mma_f16(acc[1][2 * jp],     af[1], b0);
                mma_f16(acc[0][2 * jp + 1], af[0], b1);
                mma_f16(acc[1][2 * jp + 1], af[1], b1);
                if (jp < 3) { bt[0] = btn[0]; bt[1] = btn[1]; bt[2] = btn[2]; bt[3] = btn[3]; }
            }
        }
    }
    __syncthreads();
}

// ---------------- combined QKV projection (+bias, +rope), half out (b,n,c) ---
#define QSTR 136
__global__ __launch_bounds__(256, 2)
void gemm_qkv_h(const __half* __restrict__ Aq, const __half* __restrict__ Akv,
                const __half* __restrict__ Wh,
                const float* __restrict__ bqp, const float* __restrict__ bkp,
                const float* __restrict__ bvp,
                __half* __restrict__ Qo, __half* __restrict__ Ko, __half* __restrict__ Vo) {
    extern __shared__ char smem[];
    int z = blockIdx.z;
    const __half* A = z ? Akv : Aq;
    const __half* W = Wh + (size_t)z * Cch * Cch;
    const float* bias = (z == 0) ? bqp : (z == 1) ? bkp : bvp;
    __half* Out = (z == 0) ? Qo : (z == 1) ? Ko : Vo;
    int do_rope = (z < 2);

    int m0 = blockIdx.x * 128, c0 = blockIdx.y * 128;
    float acc[2][8][4];
#pragma unroll
    for (int a = 0; a < 2; a++)
#pragma unroll
        for (int j = 0; j < 8; j++)
#pragma unroll
            for (int q = 0; q < 4; q++) acc[a][j][q] = 0.f;

    gemm_mainloop_h(A, W, smem, acc, m0, c0);

    int tid = threadIdx.x;
    int wid = tid >> 5, lane = tid & 31;
    int gid = lane >> 2, tg = lane & 3;
    int warp_m = wid >> 1, warp_n = wid & 1;

    __half* stage = (__half*)smem;
#pragma unroll
    for (int fm = 0; fm < 2; fm++) {
#pragma unroll
        for (int rr = 0; rr < 2; rr++) {
            int ml = warp_m * 32 + fm * 16 + gid + rr * 8;
            int n = (m0 + ml) & (Nn - 1);
            const float* rp = g_rope + n * 64;
#pragma unroll
            for (int j = 0; j < 8; j++) {
                int col = warp_n * 64 + j * 8 + 2 * tg;
                float v0 = acc[fm][j][rr * 2]     + __ldg(bias + c0 + col);
                float v1 = acc[fm][j][rr * 2 + 1] + __ldg(bias + c0 + col + 1);
                if (do_rope) {
                    int d = col & 63;
                    float sn = rp[d], cs = rp[d + 1];
                    float x0 = v0, x1 = v1;
                    v0 = x0 * cs - x1 * sn;
                    v1 = x0 * sn + x1 * cs;
                }
                *(__half2*)(stage + ml * QSTR + col) = __floats2half2_rn(v0, v1);
            }
        }
    }
    __syncthreads();
#pragma unroll
    for (int p = 0; p < 8; p++) {
        int idx = p * 256 + tid;
        int ml = idx >> 4, c8 = idx & 15;
        *(uint4*)(Out + (size_t)(m0 + ml) * 512 + c0 + c8 * 8) =
            *(uint4*)(stage + ml * QSTR + c8 * 8);
    }
}

// ---------------- output projection: fp32 (b,c,n), bias+residual in frag -----
#define SSTR 132
__global__ __launch_bounds__(256, 2)
void gemm_out_h(const __half* __restrict__ A, const __half* __restrict__ W,
                const float* __restrict__ bo, const __half* __restrict__ residh,
                float* __restrict__ Out) {
    extern __shared__ char smem[];
    int m0 = blockIdx.x * 128, c0 = blockIdx.y * 128;
    float acc[2][8][4];
#pragma unroll
    for (int a = 0; a < 2; a++)
#pragma unroll
        for (int j = 0; j < 8; j++)
#pragma unroll
            for (int q = 0; q < 4; q++) acc[a][j][q] = 0.f;

    gemm_mainloop_h(A, W, smem, acc, m0, c0);

    int tid = threadIdx.x;
    int wid = tid >> 5, lane = tid & 31;
    int gid = lane >> 2, tg = lane & 3;
    int warp_m = wid >> 1, warp_n = wid & 1;

    float* stage = (float*)smem;
#pragma unroll
    for (int fm = 0; fm < 2; fm++) {
        int mb = warp_m * 32 + fm * 16 + gid;
#pragma unroll
        for (int j = 0; j < 8; j++) {
            int cl = warp_n * 64 + j * 8 + 2 * tg;
            float b0 = __ldg(bo + c0 + cl);
            float b1 = __ldg(bo + c0 + cl + 1);
            float2 rLo = __half22float2(*(const __half2*)(residh + (size_t)(m0 + mb    ) * 512 + c0 + cl));
            float2 rHi = __half22float2(*(const __half2*)(residh + (size_t)(m0 + mb + 8) * 512 + c0 + cl));
            stage[(cl    ) * SSTR + mb    ] = acc[fm][j][0] + b0 + rLo.x;
            stage[(cl + 1) * SSTR + mb    ] = acc[fm][j][1] + b1 + rLo.y;
            stage[(cl    ) * SSTR + mb + 8] = acc[fm][j][2] + b0 + rHi.x;
            stage[(cl + 1) * SSTR + mb + 8] = acc[fm][j][3] + b1 + rHi.y;
        }
    }
    __syncthreads();

    int b = m0 >> 12, n0 = m0 & (Nn - 1);
    for (int t = tid; t < 128 * 32; t += 256) {
        int cl = t >> 5, mq = (t & 31) * 4;
        int c = c0 + cl;
        size_t o = ((size_t)(b * 512 + c)) * 4096 + n0 + mq;
        *(float4*)(Out + o) = *(float4*)(stage + cl * SSTR + mq);
    }
}

// ---------------- weights fp32 -> half + rope table (one launch) -------------
__global__ void prep_all(const float* __restrict__ w0, const float* __restrict__ w1,
                         const float* __restrict__ w2, const float* __restrict__ w3,
                         __half* __restrict__ dst) {
    int y = blockIdx.y;
    if (y == 4) {
        int idx = blockIdx.x * 256 + threadIdx.x;
        int n = idx >> 5, j = idx & 31;
        float inv = 1.0f / powf(10000.0f, (float)(2 * j) / 64.0f);
        float ang = (float)n * inv;
        g_rope[n * 64 + 2 * j]     = sinf(ang);
        g_rope[n * 64 + 2 * j + 1] = cosf(ang);
        return;
    }
    if (blockIdx.x >= 256) return;
    const float* src = (y == 0) ? w0 : (y == 1) ? w1 : (y == 2) ? w2 : w3;
    int i = (blockIdx.x * 256 + threadIdx.x) * 4;
    float4 v = *(const float4*)(src + i);
    __half* d = dst + (size_t)y * Cch * Cch + i;
    *(__half2*)(d)     = __floats2half2_rn(v.x, v.y);
    *(__half2*)(d + 2) = __floats2half2_rn(v.z, v.w);
}

// ---------------- fused layernorm: (b,c,n) fp32 in -> (b,n,c) half out -------
#define LSTR 72
__global__ __launch_bounds__(128)
void ln_fused(const float* __restrict__ xq, const float* __restrict__ xkv,
              const float* __restrict__ gq, const float* __restrict__ bq,
              const float* __restrict__ gkv, const float* __restrict__ bkv,
              __half* __restrict__ out_qt, __half* __restrict__ out_kvt) {
    __shared__ float gs[512], bs[512];
    __shared__ __half st[128 * LSTR];
    int z = blockIdx.z;
    const float* x   = z ? xkv : xq;
    const float* gam = z ? gkv : gq;
    const float* bet = z ? bkv : bq;
    __half* outT     = z ? out_kvt : out_qt;

    int tid = threadIdx.x;
    for (int c = tid; c < 512; c += 128) { gs[c] = gam[c]; bs[c] = bet[c]; }
    __syncthreads();

    int b = blockIdx.y;
    int n0 = blockIdx.x * 128;
    int n = n0 + tid;
    const float* xp = x + (size_t)b * Cch * Nn + n;

    float s = 0.f, sq = 0.f;
#pragma unroll 8
    for (int c = 0; c < 512; c++) { float v = xp[(size_t)c * Nn]; s += v; sq += v * v; }
    float mu   = s * (1.0f / 512.0f);
    float var  = sq * (1.0f / 512.0f) - mu * mu;
    float rstd = rsqrtf(var + 1e-5f);

    __half* obase = outT + ((size_t)b * Nn + n0) * 512;

    for (int ch = 0; ch < 8; ch++) {
#pragma unroll
        for (int cc = 0; cc < 64; cc += 2) {
            int c = ch * 64 + cc;
            float v0 = xp[(size_t)c * Nn];
            float v1 = xp[(size_t)(c + 1) * Nn];
            float y0 = (v0 - mu) * rstd * gs[c]     + bs[c];
            float y1 = (v1 - mu) * rstd * gs[c + 1] + bs[c + 1];
            *(__half2*)(st + tid * LSTR + cc) = __floats2half2_rn(y0, y1);
        }
        __syncthreads();
        for (int t = tid; t < 1024; t += 128) {
            int r = t >> 3, c4 = t & 7;
            *(uint4*)(obase + (size_t)r * 512 + ch * 64 + c4 * 8) =
                *(uint4*)(st + r * LSTR + c4 * 8);
        }
        __syncthreads();
    }
}

// ---------------- windowed attention on tensor cores -------------------------
__global__ __launch_bounds__(128)
void attn_mma(const float* __restrict__ bias_table) {
    __shared__ __align__(16) char sQ[8192];
    __shared__ __align__(16) char sK[8192];
    __shared__ __align__(16) char sV[8192];
    __shared__ float tbl[232];

    int tid = threadIdx.x;
    int w = blockIdx.x, h = blockIdx.y;
    int b = w >> 6, win = w & 63;
    int wy = win >> 3, wx = win & 7;

    for (int t = tid; t < 225; t += 128) tbl[t] = bias_table[t * 8 + h];

    uint32_t uQ = smem_u32(sQ), uK = smem_u32(sK), uV = smem_u32(sV);

    const size_t baseC = ((size_t)b * Nn) * Cch + h * 64;
#pragma unroll
    for (int p = 0; p < 4; p++) {
        int t = p * 128 + tid;
        int r = t >> 3, c4 = t & 7;
        int ri = r >> 3, ci = r & 7;
        int n = (wy * 8 + ri) * 64 + wx * 8 + ci;
        const char* src = (const char*)(g_Qh + baseC + (size_t)n * 512) + c4 * 16;
        const char* srk = (const char*)(g_Kh + baseC + (size_t)n * 512) + c4 * 16;
        const char* srv = (const char*)(g_Vh + baseC + (size_t)n * 512) + c4 * 16;
        uint32_t dst = (uint32_t)(r * 128 + ((c4 ^ (r & 7)) << 4));
        cp16(uQ + dst, src);
        cp16(uK + dst, srk);
        cp16(uV + dst, srv);
    }
    CP_COMMIT();
    CP_WAIT0();
    __syncthreads();

    int wid = tid >> 5, lane = tid & 31;
    int gid = lane >> 2, tg = lane & 3;
    int lr = lane & 7, sel = lane >> 3;
    int selLo = sel & 1, selHi = sel >> 1;
    int m0 = wid * 16;

    int rAq = m0 + selLo * 8 + lr;
    int rB0 = selLo * 8 + lr;

    float sacc[8][4];
#pragma unroll
    for (int j = 0; j < 8; j++)
#pragma unroll
        for (int q = 0; q < 4; q++) sacc[j][q] = 0.f;

#pragma unroll
    for (int kk = 0; kk < 4; kk++) {
        int chunk = 2 * kk + selHi;
        uint32_t af[4];
        ldsm4(af, uQ + (uint32_t)(rAq * 128 + ((chunk ^ (rAq & 7)) << 4)));
#pragma unroll
        for (int jp = 0; jp < 4; jp++) {
            int r = rB0 + jp * 16;
            uint32_t bt[4];
            ldsm4(bt, uK + (uint32_t)(r * 128 + ((chunk ^ (r & 7)) << 4)));
            uint32_t b0[2] = { bt[0], bt[2] };
            uint32_t b1[2] = { bt[1], bt[3] };
            mma_f16(sacc[2 * jp],     af, b0);
            mma_f16(sacc[2 * jp + 1], af, b1);
        }
    }

    int iLo = m0 + gid, iHi = iLo + 8;
    int riLo = iLo >> 3, ciLo = iLo & 7, riHi = iHi >> 3, ciHi = iHi & 7;
#pragma unroll
    for (int j = 0; j < 8; j++) {
#pragma unroll
        for (int q = 0; q < 4; q++) {
            int jc = j * 8 + 2 * tg + (q & 1);
            int rj = jc >> 3, cj = jc & 7;
            int ri = (q < 2) ? riLo : riHi;
            int ci = (q < 2) ? ciLo : ciHi;
            int idx = (ri - rj + 7) * 15 + (ci - cj + 7);
            sacc[j][q] = sacc[j][q] * 0.125f + tbl[idx];
        }
    }

    float mx0 = -1e30f, mx1 = -1e30f;
#pragma unroll
    for (int j = 0; j < 8; j++) {
        mx0 = fmaxf(mx0, fmaxf(sacc[j][0], sacc[j][1]));
        mx1 = fmaxf(mx1, fmaxf(sacc[j][2], sacc[j][3]));
    }
    mx0 = fmaxf(mx0, __shfl_xor_sync(0xffffffffu, mx0, 1));
    mx0 = fmaxf(mx0, __shfl_xor_sync(0xffffffffu, mx0, 2));
    mx1 = fmaxf(mx1, __shfl_xor_sync(0xffffffffu, mx1, 1));
    mx1 = fmaxf(mx1, __shfl_xor_sync(0xffffffffu, mx1, 2));
    float s0 = 0.f, s1 = 0.f;
#pragma unroll
    for (int j = 0; j < 8; j++) {
        sacc[j][0] = __expf(sacc[j][0] - mx0);
        sacc[j][1] = __expf(sacc[j][1] - mx0);
        sacc[j][2] = __expf(sacc[j][2] - mx1);
        sacc[j][3] = __expf(sacc[j][3] - mx1);
        s0 += sacc[j][0] + sacc[j][1];
        s1 += sacc[j][2] + sacc[j][3];
    }
    s0 += __shfl_xor_sync(0xffffffffu, s0, 1);
    s0 += __shfl_xor_sync(0xffffffffu, s0, 2);
    s1 += __shfl_xor_sync(0xffffffffu, s1, 1);
    s1 += __shfl_xor_sync(0xffffffffu, s1, 2);
    float i0v = 1.0f / s0, i1v = 1.0f / s1;
#pragma unroll
    for (int j = 0; j < 8; j++) {
        sacc[j][0] *= i0v; sacc[j][1] *= i0v;
        sacc[j][2] *= i1v; sacc[j][3] *= i1v;
    }

    float oacc[8][4];
#pragma unroll
    for (int j = 0; j < 8; j++)
#pragma unroll
        for (int q = 0; q < 4; q++) oacc[j][q] = 0.f;

#pragma unroll
    for (int kkp = 0; kkp < 4; kkp++) {
        uint32_t af[4];
        af[0] = packh2(sacc[2 * kkp][0],     sacc[2 * kkp][1]);
        af[1] = packh2(sacc[2 * kkp][2],     sacc[2 * kkp][3]);
        af[2] = packh2(sacc[2 * kkp + 1][0], sacc[2 * kkp + 1][1]);
        af[3] = packh2(sacc[2 * kkp + 1][2], sacc[2 * kkp + 1][3]);
        int j0 = kkp * 16;
#pragma unroll
        for (int dp = 0; dp < 4; dp++) {
            int r = j0 + selLo * 8 + lr;
            int chunk = 2 * dp + selHi;
            uint32_t bt[4];
            ldsm4t(bt, uV + (uint32_t)(r * 128 + ((chunk ^ (r & 7)) << 4)));
            uint32_t b0[2] = { bt[0], bt[1] };
            uint32_t b1[2] = { bt[2], bt[3] };
            mma_f16(oacc[2 * dp],     af, b0);
            mma_f16(oacc[2 * dp + 1], af, b1);
        }
    }

    // stage O into sQ (dead) with the same XOR swizzle, then dense copy-out
#pragma unroll
    for (int dc = 0; dc < 8; dc++) {
        uint32_t hLo = packh2(oacc[dc][0], oacc[dc][1]);
        uint32_t hHi = packh2(oacc[dc][2], oacc[dc][3]);
        asm volatile("st.shared.b32 [%0], %1;" ::
            "r"(uQ + (uint32_t)(iLo * 128 + ((dc ^ (iLo & 7)) << 4) + 4 * tg)), "r"(hLo) : "memory");
        asm volatile("st.shared.b32 [%0], %1;" ::
            "r"(uQ + (uint32_t)(iHi * 128 + ((dc ^ (iHi & 7)) << 4) + 4 * tg)), "r"(hHi) : "memory");
    }
    __syncthreads();
#pragma unroll
    for (int t0 = 0; t0 < 4; t0++) {
        int t = t0 * 128 + tid;
        int i = t >> 3, c8 = t & 7;
        int n = (wy * 8 + (i >> 3)) * 64 + wx * 8 + (i & 7);
        *(uint4*)((char*)(g_attn_h + baseC + (size_t)n * 512) + c8 * 16) =
            *(uint4*)(sQ + i * 128 + ((c8 ^ (i & 7)) << 4));
    }
}

// ---------------- launch -----------------------------------------------------
extern "C" void kernel_launch(void* const* d_in, const int* in_sizes, int n_in,
                              void* d_out, int out_size) {
    const float* q          = (const float*)d_in[0];
    const float* kv         = (const float*)d_in[1];
    const float* gq         = (const float*)d_in[2];
    const float* bqln       = (const float*)d_in[3];
    const float* gkv        = (const float*)d_in[4];
    const float* bkvln      = (const float*)d_in[5];
    const float* Wq         = (const float*)d_in[6];
    const float* bq         = (const float*)d_in[7];
    const float* Wk         = (const float*)d_in[8];
    const float* bk         = (const float*)d_in[9];
    const float* Wv         = (const float*)d_in[10];
    const float* bv         = (const float*)d_in[11];
    const float* Wo         = (const float*)d_in[12];
    const float* bo         = (const float*)d_in[13];
    const float* bias_table = (const float*)d_in[14];
    float* out = (float*)d_out;

    __half *p_qnt, *p_kvnt, *p_Q, *p_K, *p_V, *p_attn, *p_Wh;
    cudaGetSymbolAddress((void**)&p_qnt,  g_qnt_h);
    cudaGetSymbolAddress((void**)&p_kvnt, g_kvnt_h);
    cudaGetSymbolAddress((void**)&p_Q,    g_Qh);
    cudaGetSymbolAddress((void**)&p_K,    g_Kh);
    cudaGetSymbolAddress((void**)&p_V,    g_Vh);
    cudaGetSymbolAddress((void**)&p_attn, g_attn_h);
    cudaGetSymbolAddress((void**)&p_Wh,   g_Wh);

    cudaFuncSetAttribute(gemm_qkv_h, cudaFuncAttributeMaxDynamicSharedMemorySize, GSMEM);
    cudaFuncSetAttribute(gemm_out_h, cudaFuncAttributeMaxDynamicSharedMemorySize, GSMEM);

    prep_all<<<dim3(512, 5), 256>>>(Wq, Wk, Wv, Wo, p_Wh);

    ln_fused<<<dim3(Nn / 128, Bb, 2), 128>>>(q, kv, gq, bqln, gkv, bkvln,
                                             p_qnt, p_kvnt);

    gemm_qkv_h<<<dim3(Bb * Nn / 128, Cch / 128, 3), 256, GSMEM>>>(
        p_qnt, p_kvnt, p_Wh, bq, bk, bv, p_Q, p_K, p_V);

    attn_mma<<<dim3(Bb * 64, NHh), 128>>>(bias_table);

    gemm_out_h<<<dim3(Bb * Nn / 128, Cch / 128), 256, GSMEM>>>(
        p_attn, p_Wh + 3 * (size_t)Cch * Cch, bo, p_qnt, out);
}

// round 14
// speedup vs baseline: 1.7407x; 1.1487x over previous
#include <cuda_runtime.h>
#include <cuda_fp16.h>
#include <cstdint>
#include <math.h>

#define Bb   8
#define Cch  512
#define Nn   4096
#define NHh  8
#define Dd   64

// ---------------- scratch ----------------------------------------------------
__device__ __half g_qnt_h [Bb*Nn*Cch];   // normalized q , (b,n,c) half (GEMM A + residual)
__device__ __half g_kvnt_h[Bb*Nn*Cch];   // normalized kv, (b,n,c) half
__device__ __half g_Qh    [Bb*Nn*Cch];   // (b,n,c) after rope
__device__ __half g_Kh    [Bb*Nn*Cch];
__device__ __half g_Vh    [Bb*Nn*Cch];
__device__ __half g_attn_h[Bb*Nn*Cch];   // attention out, (b,n,c)
__device__ __half g_Wh    [4*Cch*Cch];   // rounded weights: Wq,Wk,Wv,Wo
__device__ float  g_rope  [Nn*Dd];

// ---------------- PTX helpers ------------------------------------------------
__device__ __forceinline__ uint32_t smem_u32(const void* p) {
    uint32_t a;
    asm("{ .reg .u64 t; cvta.to.shared.u64 t, %1; cvt.u32.u64 %0, t; }" : "=r"(a) : "l"(p));
    return a;
}
__device__ __forceinline__ void cp16(uint32_t dst, const void* src) {
    asm volatile("cp.async.cg.shared.global [%0], [%1], 16;" :: "r"(dst), "l"(src));
}
#define CP_COMMIT() asm volatile("cp.async.commit_group;" ::: "memory")
#define CP_WAIT1()  asm volatile("cp.async.wait_group 1;" ::: "memory")
#define CP_WAIT0()  asm volatile("cp.async.wait_group 0;" ::: "memory")

__device__ __forceinline__ void mma_f16(float* d, const uint32_t* a, const uint32_t* b) {
    asm volatile(
        "mma.sync.aligned.m16n8k16.row.col.f32.f16.f16.f32 "
        "{%0,%1,%2,%3}, {%4,%5,%6,%7}, {%8,%9}, {%0,%1,%2,%3};"
        : "+f"(d[0]), "+f"(d[1]), "+f"(d[2]), "+f"(d[3])
        : "r"(a[0]), "r"(a[1]), "r"(a[2]), "r"(a[3]), "r"(b[0]), "r"(b[1]));
}
__device__ __forceinline__ void ldsm4(uint32_t* r, uint32_t addr) {
    asm volatile("ldmatrix.sync.aligned.m8n8.x4.shared.b16 {%0,%1,%2,%3}, [%4];"
        : "=r"(r[0]), "=r"(r[1]), "=r"(r[2]), "=r"(r[3]) : "r"(addr));
}
__device__ __forceinline__ void ldsm4t(uint32_t* r, uint32_t addr) {
    asm volatile("ldmatrix.sync.aligned.m8n8.x4.trans.shared.b16 {%0,%1,%2,%3}, [%4];"
        : "=r"(r[0]), "=r"(r[1]), "=r"(r[2]), "=r"(r[3]) : "r"(addr));
}
__device__ __forceinline__ uint32_t packh2(float a, float b) {
    __half2 h = __floats2half2_rn(a, b);
    return *(uint32_t*)&h;
}
__device__ __forceinline__ uint32_t rowc(int r) {
    return (uint32_t)(r * 128 + ((r & 7) << 4));
}

#define STAGE_B 32768
#define GSMEM   (3 * STAGE_B)

__device__ __forceinline__ void issue_stage(uint32_t sbuf, const char* as, const char* ws,
                                            uint32_t w0) {
#pragma unroll
    for (int p = 0; p < 4; p++) {
        cp16(sbuf + w0 + p * 4096,         as + p * 32768);
        cp16(sbuf + 16384 + w0 + p * 4096, ws + p * 32768);
    }
}

// ---------------- mainloop: D[128m x 128c] = A[128x512] x W[128x512]^T -------
__device__ __forceinline__ void gemm_mainloop_h(const __half* __restrict__ A,
                                                const __half* __restrict__ W,
                                                char* smem, float acc[2][8][4],
                                                int m0, int c0) {
    uint32_t sb = smem_u32(smem);
    int tid = threadIdx.x;
    int wid = tid >> 5, lane = tid & 31;
    int warp_m = wid >> 1, warp_n = wid & 1;
    int lr = lane & 7, sel = lane >> 3;
    int selLo = sel & 1, selHi = sel >> 1;

    uint32_t rowA0 = rowc(warp_m * 32 + selLo * 8 + lr);
    uint32_t rowA1 = rowc(warp_m * 32 + selLo * 8 + lr + 16);
    uint32_t rowB[4];
#pragma unroll
    for (int jp = 0; jp < 4; jp++)
        rowB[jp] = rowc(warp_n * 64 + selLo * 8 + lr + jp * 16);

    const char* Ab = (const char*)(A + (size_t)m0 * 512);
    const char* Wb = (const char*)(W + (size_t)c0 * 512);
    int r0 = tid >> 3, c4w = tid & 7;
    uint32_t w0 = (uint32_t)(r0 * 128 + ((c4w ^ (r0 & 7)) << 4));
    uint32_t so = (uint32_t)(r0 * 1024 + c4w * 16);

    issue_stage(sb,           Ab + so,       Wb + so,       w0); CP_COMMIT();
    issue_stage(sb + STAGE_B, Ab + so + 128, Wb + so + 128, w0); CP_COMMIT();

    for (int s = 0; s < 8; s++) {
        CP_WAIT1();
        __syncthreads();
        if (s + 2 < 8)
            issue_stage(sb + ((s + 2) % 3) * STAGE_B,
                        Ab + so + (s + 2) * 128, Wb + so + (s + 2) * 128, w0);
        CP_COMMIT();

        uint32_t baseA = sb + (s % 3) * STAGE_B;
        uint32_t baseB = baseA + 16384;
#pragma unroll
        for (int kk = 0; kk < 4; kk++) {
            uint32_t xm = (uint32_t)((2 * kk + selHi) << 4);
            uint32_t af[2][4];
            ldsm4(af[0], baseA + (rowA0 ^ xm));
            ldsm4(af[1], baseA + (rowA1 ^ xm));
            uint32_t bt[4];
            ldsm4(bt, baseB + (rowB[0] ^ xm));
#pragma unroll
            for (int jp = 0; jp < 4; jp++) {
                uint32_t btn[4];
                if (jp < 3) ldsm4(btn, baseB + (rowB[jp + 1] ^ xm));
                uint32_t b0[2] = { bt[0], bt[2] };
                uint32_t b1[2] = { bt[1], bt[3] };
                mma_f16(acc[0][2 * jp],     af[0], b0);
                mma_f16(acc[1][2 * jp],     af[1], b0);
                mma_f16(acc[0][2 * jp + 1], af[0], b1);
                mma_f16(acc[1][2 * jp + 1], af[1], b1);
                if (jp < 3) { bt[0] = btn[0]; bt[1] = btn[1]; bt[2] = btn[2]; bt[3] = btn[3]; }
            }
        }
    }
    __syncthreads();
}

// ---------------- combined QKV projection (+bias, +rope), half out (b,n,c) ---
#define QSTR 136
__global__ __launch_bounds__(256, 2)
void gemm_qkv_h(const __half* __restrict__ Aq, const __half* __restrict__ Akv,
                const __half* __restrict__ Wh,
                const float* __restrict__ bqp, const float* __restrict__ bkp,
                const float* __restrict__ bvp,
                __half* __restrict__ Qo, __half* __restrict__ Ko, __half* __restrict__ Vo) {
    extern __shared__ char smem[];
    int z = blockIdx.z;
    const __half* A = z ? Akv : Aq;
    const __half* W = Wh + (size_t)z * Cch * Cch;
    const float* bias = (z == 0) ? bqp : (z == 1) ? bkp : bvp;
    __half* Out = (z == 0) ? Qo : (z == 1) ? Ko : Vo;
    int do_rope = (z < 2);

    int m0 = blockIdx.x * 128, c0 = blockIdx.y * 128;
    float acc[2][8][4];
#pragma unroll
    for (int a = 0; a < 2; a++)
#pragma unroll
        for (int j = 0; j < 8; j++)
#pragma unroll
            for (int q = 0; q < 4; q++) acc[a][j][q] = 0.f;

    gemm_mainloop_h(A, W, smem, acc, m0, c0);

    int tid = threadIdx.x;
    int wid = tid >> 5, lane = tid & 31;
    int gid = lane >> 2, tg = lane & 3;
    int warp_m = wid >> 1, warp_n = wid & 1;

    __half* stage = (__half*)smem;
#pragma unroll
    for (int fm = 0; fm < 2; fm++) {
#pragma unroll
        for (int rr = 0; rr < 2; rr++) {
            int ml = warp_m * 32 + fm * 16 + gid + rr * 8;
            int n = (m0 + ml) & (Nn - 1);
            const float* rp = g_rope + n * 64;
#pragma unroll
            for (int j = 0; j < 8; j++) {
                int col = warp_n * 64 + j * 8 + 2 * tg;
                float v0 = acc[fm][j][rr * 2]     + __ldg(bias + c0 + col);
                float v1 = acc[fm][j][rr * 2 + 1] + __ldg(bias + c0 + col + 1);
                if (do_rope) {
                    int d = col & 63;
                    float sn = rp[d], cs = rp[d + 1];
                    float x0 = v0, x1 = v1;
                    v0 = x0 * cs - x1 * sn;
                    v1 = x0 * sn + x1 * cs;
                }
                *(__half2*)(stage + ml * QSTR + col) = __floats2half2_rn(v0, v1);
            }
        }
    }
    __syncthreads();
#pragma unroll
    for (int p = 0; p < 8; p++) {
        int idx = p * 256 + tid;
        int ml = idx >> 4, c8 = idx & 15;
        *(uint4*)(Out + (size_t)(m0 + ml) * 512 + c0 + c8 * 8) =
            *(uint4*)(stage + ml * QSTR + c8 * 8);
    }
}

// ---------------- output projection: fp32 (b,c,n), bias+residual in frag -----
#define SSTR 132
__global__ __launch_bounds__(256, 2)
void gemm_out_h(const __half* __restrict__ A, const __half* __restrict__ W,
                const float* __restrict__ bo, const __half* __restrict__ residh,
                float* __restrict__ Out) {
    extern __shared__ char smem[];
    int m0 = blockIdx.x * 128, c0 = blockIdx.y * 128;
    float acc[2][8][4];
#pragma unroll
    for (int a = 0; a < 2; a++)
#pragma unroll
        for (int j = 0; j < 8; j++)
#pragma unroll
            for (int q = 0; q < 4; q++) acc[a][j][q] = 0.f;

    gemm_mainloop_h(A, W, smem, acc, m0, c0);

    int tid = threadIdx.x;
    int wid = tid >> 5, lane = tid & 31;
    int gid = lane >> 2, tg = lane & 3;
    int warp_m = wid >> 1, warp_n = wid & 1;

    float* stage = (float*)smem;
#pragma unroll
    for (int fm = 0; fm < 2; fm++) {
        int mb = warp_m * 32 + fm * 16 + gid;
#pragma unroll
        for (int j = 0; j < 8; j++) {
            int cl = warp_n * 64 + j * 8 + 2 * tg;
            float b0 = __ldg(bo + c0 + cl);
            float b1 = __ldg(bo + c0 + cl + 1);
            float2 rLo = __half22float2(*(const __half2*)(residh + (size_t)(m0 + mb    ) * 512 + c0 + cl));
            float2 rHi = __half22float2(*(const __half2*)(residh + (size_t)(m0 + mb + 8) * 512 + c0 + cl));
            stage[(cl    ) * SSTR + mb    ] = acc[fm][j][0] + b0 + rLo.x;
            stage[(cl + 1) * SSTR + mb    ] = acc[fm][j][1] + b1 + rLo.y;
            stage[(cl    ) * SSTR + mb + 8] = acc[fm][j][2] + b0 + rHi.x;
            stage[(cl + 1) * SSTR + mb + 8] = acc[fm][j][3] + b1 + rHi.y;
        }
    }
    __syncthreads();

    int b = m0 >> 12, n0 = m0 & (Nn - 1);
    for (int t = tid; t < 128 * 32; t += 256) {
        int cl = t >> 5, mq = (t & 31) * 4;
        int c = c0 + cl;
        size_t o = ((size_t)(b * 512 + c)) * 4096 + n0 + mq;
        *(float4*)(Out + o) = *(float4*)(stage + cl * SSTR + mq);
    }
}

// ---------------- weights fp32 -> half + rope table (one launch) -------------
__global__ void prep_all(const float* __restrict__ w0, const float* __restrict__ w1,
                         const float* __restrict__ w2, const float* __restrict__ w3,
                         __half* __restrict__ dst) {
    int y = blockIdx.y;
    if (y == 4) {
        int idx = blockIdx.x * 256 + threadIdx.x;
        int n = idx >> 5, j = idx & 31;
        float inv = 1.0f / powf(10000.0f, (float)(2 * j) / 64.0f);
        float ang = (float)n * inv;
        g_rope[n * 64 + 2 * j]     = sinf(ang);
        g_rope[n * 64 + 2 * j + 1] = cosf(ang);
        return;
    }
    if (blockIdx.x >= 256) return;
    const float* src = (y == 0) ? w0 : (y == 1) ? w1 : (y == 2) ? w2 : w3;
    int i = (blockIdx.x * 256 + threadIdx.x) * 4;
    float4 v = *(const float4*)(src + i);
    __half* d = dst + (size_t)y * Cch * Cch + i;
    *(__half2*)(d)     = __floats2half2_rn(v.x, v.y);
    *(__half2*)(d + 2) = __floats2half2_rn(v.z, v.w);
}

// ---------------- single-pass layernorm: (b,c,n) fp32 -> (b,n,c) half --------
// block = 32 tokens x 512 channels; values held in registers (one global read)
#define LPAD 264   // uint32 words per staged token row (1056B, 16B aligned)
__global__ __launch_bounds__(256)
void ln_onepass(const float* __restrict__ xq, const float* __restrict__ xkv,
                const float* __restrict__ gq, const float* __restrict__ bq,
                const float* __restrict__ gkv, const float* __restrict__ bkv,
                __half* __restrict__ out_qt, __half* __restrict__ out_kvt) {
    __shared__ float gs[512], bs[512];
    __shared__ float reds[8][33], redq[8][33];
    __shared__ __align__(16) uint32_t st[32 * LPAD];

    int z = blockIdx.z;
    const float* x   = z ? xkv : xq;
    const float* gam = z ? gkv : gq;
    const float* bet = z ? bkv : bq;
    __half* outT     = z ? out_kvt : out_qt;

    int tid = threadIdx.x;
    int tx = tid & 31, ty = tid >> 5;
    for (int c = tid; c < 512; c += 256) { gs[c] = gam[c]; bs[c] = bet[c]; }

    int b = blockIdx.y;
    int n0 = blockIdx.x * 32;
    const float* xp = x + (size_t)b * Cch * Nn + n0 + tx;

    // one pass: load 64 channels (pairs 2*ty+16k) into registers
    float v[64];
    float s = 0.f, sq = 0.f;
#pragma unroll
    for (int k = 0; k < 32; k++) {
        int c = 2 * ty + 16 * k;
        float a0 = xp[(size_t)c * Nn];
        float a1 = xp[(size_t)(c + 1) * Nn];
        v[2 * k] = a0; v[2 * k + 1] = a1;
        s += a0 + a1;
        sq += a0 * a0 + a1 * a1;
    }
    reds[ty][tx] = s;
    redq[ty][tx] = sq;
    __syncthreads();
    float S = 0.f, Q = 0.f;
#pragma unroll
    for (int u = 0; u < 8; u++) { S += reds[u][tx]; Q += redq[u][tx]; }
    float mu   = S * (1.0f / 512.0f);
    float var  = Q * (1.0f / 512.0f) - mu * mu;
    float rstd = rsqrtf(var + 1e-5f);

    // scale + stage as half2
#pragma unroll
    for (int k = 0; k < 32; k++) {
        int c = 2 * ty + 16 * k;
        float y0 = (v[2 * k]     - mu) * rstd * gs[c]     + bs[c];
        float y1 = (v[2 * k + 1] - mu) * rstd * gs[c + 1] + bs[c + 1];
        st[tx * LPAD + ty + 8 * k] = packh2(y0, y1);
    }
    __syncthreads();

    // dense write-out: 32 rows x 1024B
    __half* obase = outT + ((size_t)b * Nn + n0) * 512;
#pragma unroll
    for (int p = 0; p < 8; p++) {
        int idx = p * 256 + tid;          // 0..2047 (16B chunks)
        int r = idx >> 6, w16 = idx & 63;
        *(uint4*)((char*)(obase + (size_t)r * 512) + w16 * 16) =
            *(const uint4*)(st + r * LPAD + w16 * 4);
    }
}

// ---------------- windowed attention on tensor cores -------------------------
__global__ __launch_bounds__(128)
void attn_mma(const float* __restrict__ bias_table) {
    __shared__ __align__(16) char sQ[8192];
    __shared__ __align__(16) char sK[8192];
    __shared__ __align__(16) char sV[8192];
    __shared__ float tbl[232];

    int tid = threadIdx.x;
    int w = blockIdx.x, h = blockIdx.y;
    int b = w >> 6, win = w & 63;
    int wy = win >> 3, wx = win & 7;

    for (int t = tid; t < 225; t += 128) tbl[t] = bias_table[t * 8 + h];

    uint32_t uQ = smem_u32(sQ), uK = smem_u32(sK), uV = smem_u32(sV);

    const size_t baseC = ((size_t)b * Nn) * Cch + h * 64;
#pragma unroll
    for (int p = 0; p < 4; p++) {
        int t = p * 128 + tid;
        int r = t >> 3, c4 = t & 7;
        int ri = r >> 3, ci = r & 7;
        int n = (wy * 8 + ri) * 64 + wx * 8 + ci;
        const char* src = (const char*)(g_Qh + baseC + (size_t)n * 512) + c4 * 16;
        const char* srk = (const char*)(g_Kh + baseC + (size_t)n * 512) + c4 * 16;
        const char* srv = (const char*)(g_Vh + baseC + (size_t)n * 512) + c4 * 16;
        uint32_t dst = (uint32_t)(r * 128 + ((c4 ^ (r & 7)) << 4));
        cp16(uQ + dst, src);
        cp16(uK + dst, srk);
        cp16(uV + dst, srv);
    }
    CP_COMMIT();
    CP_WAIT0();
    __syncthreads();

    int wid = tid >> 5, lane = tid & 31;
    int gid = lane >> 2, tg = lane & 3;
    int lr = lane & 7, sel = lane >> 3;
    int selLo = sel & 1, selHi = sel >> 1;
    int m0 = wid * 16;

    int rAq = m0 + selLo * 8 + lr;
    int rB0 = selLo * 8 + lr;

    float sacc[8][4];
#pragma unroll
    for (int j = 0; j < 8; j++)
#pragma unroll
        for (int q = 0; q < 4; q++) sacc[j][q] = 0.f;

#pragma unroll
    for (int kk = 0; kk < 4; kk++) {
        int chunk = 2 * kk + selHi;
        uint32_t af[4];
        ldsm4(af, uQ + (uint32_t)(rAq * 128 + ((chunk ^ (rAq & 7)) << 4)));
#pragma unroll
        for (int jp = 0; jp < 4; jp++) {
            int r = rB0 + jp * 16;
            uint32_t bt[4];
            ldsm4(bt, uK + (uint32_t)(r * 128 + ((chunk ^ (r & 7)) << 4)));
            uint32_t b0[2] = { bt[0], bt[2] };
            uint32_t b1[2] = { bt[1], bt[3] };
            mma_f16(sacc[2 * jp],     af, b0);
            mma_f16(sacc[2 * jp + 1], af, b1);
        }
    }

    int iLo = m0 + gid, iHi = iLo + 8;
    int riLo = iLo >> 3, ciLo = iLo & 7, riHi = iHi >> 3, ciHi = iHi & 7;
#pragma unroll
    for (int j = 0; j < 8; j++) {
#pragma unroll
        for (int q = 0; q < 4; q++) {
            int jc = j * 8 + 2 * tg + (q & 1);
            int rj = jc >> 3, cj = jc & 7;
            int ri = (q < 2) ? riLo : riHi;
            int ci = (q < 2) ? ciLo : ciHi;
            int idx = (ri - rj + 7) * 15 + (ci - cj + 7);
            sacc[j][q] = sacc[j][q] * 0.125f + tbl[idx];
        }
    }

    float mx0 = -1e30f, mx1 = -1e30f;
#pragma unroll
    for (int j = 0; j < 8; j++) {
        mx0 = fmaxf(mx0, fmaxf(sacc[j][0], sacc[j][1]));
        mx1 = fmaxf(mx1, fmaxf(sacc[j][2], sacc[j][3]));
    }
    mx0 = fmaxf(mx0, __shfl_xor_sync(0xffffffffu, mx0, 1));
    mx0 = fmaxf(mx0, __shfl_xor_sync(0xffffffffu, mx0, 2));
    mx1 = fmaxf(mx1, __shfl_xor_sync(0xffffffffu, mx1, 1));
    mx1 = fmaxf(mx1, __shfl_xor_sync(0xffffffffu, mx1, 2));
    float s0 = 0.f, s1 = 0.f;
#pragma unroll
    for (int j = 0; j < 8; j++) {
        sacc[j][0] = __expf(sacc[j][0] - mx0);
        sacc[j][1] = __expf(sacc[j][1] - mx0);
        sacc[j][2] = __expf(sacc[j][2] - mx1);
        sacc[j][3] = __expf(sacc[j][3] - mx1);
        s0 += sacc[j][0] + sacc[j][1];
        s1 += sacc[j][2] + sacc[j][3];
    }
    s0 += __shfl_xor_sync(0xffffffffu, s0, 1);
    s0 += __shfl_xor_sync(0xffffffffu, s0, 2);
    s1 += __shfl_xor_sync(0xffffffffu, s1, 1);
    s1 += __shfl_xor_sync(0xffffffffu, s1, 2);
    float i0v = 1.0f / s0, i1v = 1.0f / s1;
#pragma unroll
    for (int j = 0; j < 8; j++) {
        sacc[j][0] *= i0v; sacc[j][1] *= i0v;
        sacc[j][2] *= i1v; sacc[j][3] *= i1v;
    }

    float oacc[8][4];
#pragma unroll
    for (int j = 0; j < 8; j++)
#pragma unroll
        for (int q = 0; q < 4; q++) oacc[j][q] = 0.f;

#pragma unroll
    for (int kkp = 0; kkp < 4; kkp++) {
        uint32_t af[4];
        af[0] = packh2(sacc[2 * kkp][0],     sacc[2 * kkp][1]);
        af[1] = packh2(sacc[2 * kkp][2],     sacc[2 * kkp][3]);
        af[2] = packh2(sacc[2 * kkp + 1][0], sacc[2 * kkp + 1][1]);
        af[3] = packh2(sacc[2 * kkp + 1][2], sacc[2 * kkp + 1][3]);
        int j0 = kkp * 16;
#pragma unroll
        for (int dp = 0; dp < 4; dp++) {
            int r = j0 + selLo * 8 + lr;
            int chunk = 2 * dp + selHi;
            uint32_t bt[4];
            ldsm4t(bt, uV + (uint32_t)(r * 128 + ((chunk ^ (r & 7)) << 4)));
            uint32_t b0[2] = { bt[0], bt[1] };
            uint32_t b1[2] = { bt[2], bt[3] };
            mma_f16(oacc[2 * dp],     af, b0);
            mma_f16(oacc[2 * dp + 1], af, b1);
        }
    }

    // stage O into sQ (dead) with the same XOR swizzle, then dense copy-out
#pragma unroll
    for (int dc = 0; dc < 8; dc++) {
        uint32_t hLo = packh2(oacc[dc][0], oacc[dc][1]);
        uint32_t hHi = packh2(oacc[dc][2], oacc[dc][3]);
        asm volatile("st.shared.b32 [%0], %1;" ::
            "r"(uQ + (uint32_t)(iLo * 128 + ((dc ^ (iLo & 7)) << 4) + 4 * tg)), "r"(hLo) : "memory");
        asm volatile("st.shared.b32 [%0], %1;" ::
            "r"(uQ + (uint32_t)(iHi * 128 + ((dc ^ (iHi & 7)) << 4) + 4 * tg)), "r"(hHi) : "memory");
    }
    __syncthreads();
#pragma unroll
    for (int t0 = 0; t0 < 4; t0++) {
        int t = t0 * 128 + tid;
        int i = t >> 3, c8 = t & 7;
        int n = (wy * 8 + (i >> 3)) * 64 + wx * 8 + (i & 7);
        *(uint4*)((char*)(g_attn_h + baseC + (size_t)n * 512) + c8 * 16) =
            *(uint4*)(sQ + i * 128 + ((c8 ^ (i & 7)) << 4));
    }
}

// ---------------- launch -----------------------------------------------------
extern "C" void kernel_launch(void* const* d_in, const int* in_sizes, int n_in,
                              void* d_out, int out_size) {
    const float* q          = (const float*)d_in[0];
    const float* kv         = (const float*)d_in[1];
    const float* gq         = (const float*)d_in[2];
    const float* bqln       = (const float*)d_in[3];
    const float* gkv        = (const float*)d_in[4];
    const float* bkvln      = (const float*)d_in[5];
    const float* Wq         = (const float*)d_in[6];
    const float* bq         = (const float*)d_in[7];
    const float* Wk         = (const float*)d_in[8];
    const float* bk         = (const float*)d_in[9];
    const float* Wv         = (const float*)d_in[10];
    const float* bv         = (const float*)d_in[11];
    const float* Wo         = (const float*)d_in[12];
    const float* bo         = (const float*)d_in[13];
    const float* bias_table = (const float*)d_in[14];
    float* out = (float*)d_out;

    __half *p_qnt, *p_kvnt, *p_Q, *p_K, *p_V, *p_attn, *p_Wh;
    cudaGetSymbolAddress((void**)&p_qnt,  g_qnt_h);
    cudaGetSymbolAddress((void**)&p_kvnt, g_kvnt_h);
    cudaGetSymbolAddress((void**)&p_Q,    g_Qh);
    cudaGetSymbolAddress((void**)&p_K,    g_Kh);
    cudaGetSymbolAddress((void**)&p_V,    g_Vh);
    cudaGetSymbolAddress((void**)&p_attn, g_attn_h);
    cudaGetSymbolAddress((void**)&p_Wh,   g_Wh);

    cudaFuncSetAttribute(gemm_qkv_h, cudaFuncAttributeMaxDynamicSharedMemorySize, GSMEM);
    cudaFuncSetAttribute(gemm_out_h, cudaFuncAttributeMaxDynamicSharedMemorySize, GSMEM);

    prep_all<<<dim3(512, 5), 256>>>(Wq, Wk, Wv, Wo, p_Wh);

    ln_onepass<<<dim3(Nn / 32, Bb, 2), 256>>>(q, kv, gq, bqln, gkv, bkvln,
                                              p_qnt, p_kvnt);

    gemm_qkv_h<<<dim3(Bb * Nn / 128, Cch / 128, 3), 256, GSMEM>>>(
        p_qnt, p_kvnt, p_Wh, bq, bk, bv, p_Q, p_K, p_V);

    attn_mma<<<dim3(Bb * 64, NHh), 128>>>(bias_table);

    gemm_out_h<<<dim3(Bb * Nn / 128, Cch / 128), 256, GSMEM>>>(
        p_attn, p_Wh + 3 * (size_t)Cch * Cch, bo, p_qnt, out);
}